// round 1
// baseline (speedup 1.0000x reference)
#include <cuda_runtime.h>
#include <math.h>
#include <stdint.h>

// ---------------- problem constants ----------------
constexpr int B  = 4;
constexpr int S  = 2048;
constexpr int E  = 1024;
constexpr int CS = 16;
constexpr int NC = 8;
constexpr int H  = 16;
constexpr int D  = E + CS;      // 1040
constexpr int DH = D / H;       // 65
constexpr int DFF = 4 * E;      // 4096
constexpr int MT = B * S;       // 8192 tokens

// ---------------- scratch (static device memory, no allocs) ----------------
constexpr size_t XC_SZ = (size_t)MT * D;        // 8,519,680
constexpr size_t HE_SZ = (size_t)MT * E;        // 8,388,608
constexpr size_t FF_SZ = (size_t)MT * DFF;      // 33,554,432

constexpr size_t OFF_XC = 0;
constexpr size_t OFF_Q  = OFF_XC + XC_SZ;
constexpr size_t OFF_V  = OFF_Q  + XC_SZ;
constexpr size_t OFF_K  = OFF_V  + XC_SZ;
constexpr size_t OFF_O  = OFF_K  + XC_SZ;
constexpr size_t OFF_H  = OFF_O  + XC_SZ;
constexpr size_t OFF_FF = OFF_H  + HE_SZ;
constexpr size_t OFF_Y  = OFF_FF + FF_SZ;
constexpr size_t SCRATCH_TOTAL = OFF_Y + HE_SZ; // 92,930,048 floats (~372 MB)

__device__ float g_scratch[SCRATCH_TOTAL];

// ---------------- block reduction helper (256 threads) ----------------
__device__ __forceinline__ float blk_sum256(float v, float* red8) {
    #pragma unroll
    for (int o = 16; o > 0; o >>= 1) v += __shfl_xor_sync(0xffffffffu, v, o);
    __syncthreads();   // protect red8 reuse across consecutive calls
    if ((threadIdx.x & 31) == 0) red8[threadIdx.x >> 5] = v;
    __syncthreads();
    if (threadIdx.x == 0) {
        float t = 0.f;
        #pragma unroll
        for (int i = 0; i < 8; i++) t += red8[i];
        red8[0] = t;
    }
    __syncthreads();
    return red8[0];
}

// ---------------- LayerNorm(x) + concat conditioning -> xc ----------------
__global__ void ln_concat_kernel(const float* __restrict__ x,
                                 const float* __restrict__ cond,
                                 const float* __restrict__ g,
                                 const float* __restrict__ bta,
                                 float* __restrict__ xc) {
    __shared__ float red8[8];
    const int s   = blockIdx.x;
    const int tid = threadIdx.x;
    const float* xr = x + (size_t)s * E;
    float v0 = xr[tid], v1 = xr[tid + 256], v2 = xr[tid + 512], v3 = xr[tid + 768];
    float mean = blk_sum256(v0 + v1 + v2 + v3, red8) * (1.0f / E);
    float d0 = v0 - mean, d1 = v1 - mean, d2 = v2 - mean, d3 = v3 - mean;
    float var = blk_sum256(d0 * d0 + d1 * d1 + d2 * d2 + d3 * d3, red8) * (1.0f / E);
    float rstd = rsqrtf(var + 1e-5f);
    float* xo = xc + (size_t)s * D;
    xo[tid      ] = d0 * rstd * g[tid      ] + bta[tid      ];
    xo[tid + 256] = d1 * rstd * g[tid + 256] + bta[tid + 256];
    xo[tid + 512] = d2 * rstd * g[tid + 512] + bta[tid + 512];
    xo[tid + 768] = d3 * rstd * g[tid + 768] + bta[tid + 768];
    if (tid < CS) xo[E + tid] = cond[(size_t)s * CS + tid];
}

// ---------------- final LayerNorm(y) -> out ----------------
__global__ void ln_final_kernel(const float* __restrict__ y,
                                const float* __restrict__ g,
                                const float* __restrict__ bta,
                                float* __restrict__ out) {
    __shared__ float red8[8];
    const int s   = blockIdx.x;
    const int tid = threadIdx.x;
    const float* yr = y + (size_t)s * E;
    float v0 = yr[tid], v1 = yr[tid + 256], v2 = yr[tid + 512], v3 = yr[tid + 768];
    float mean = blk_sum256(v0 + v1 + v2 + v3, red8) * (1.0f / E);
    float d0 = v0 - mean, d1 = v1 - mean, d2 = v2 - mean, d3 = v3 - mean;
    float var = blk_sum256(d0 * d0 + d1 * d1 + d2 * d2 + d3 * d3, red8) * (1.0f / E);
    float rstd = rsqrtf(var + 1e-5f);
    float* o = out + (size_t)s * E;
    o[tid      ] = d0 * rstd * g[tid      ] + bta[tid      ];
    o[tid + 256] = d1 * rstd * g[tid + 256] + bta[tid + 256];
    o[tid + 512] = d2 * rstd * g[tid + 512] + bta[tid + 512];
    o[tid + 768] = d3 * rstd * g[tid + 768] + bta[tid + 768];
}

// ---------------- generic SGEMM: C = A(MTxK) * W^T (W is NxK row-major) ----------------
// MODE 0: C = acc + bias
// MODE 1: C = relu(acc + bias)
// MODE 2: C = acc + bias + extra[m*eld + n]            (residual add)
// MODE 3: C = (INIT?0:C) + extra[m*eld] * (acc + bias) (conditioned-K accumulate)
template <int MODE, bool INIT>
__global__ void sgemm_kernel(const float* __restrict__ A, int lda,
                             const float* __restrict__ W, int ldw,
                             const float* __restrict__ bias,
                             float* __restrict__ C, int ldc,
                             int N_, int K_,
                             const float* __restrict__ extra, int eld) {
    __shared__ float As[16][65];
    __shared__ float Bs[16][65];
    const int m0  = blockIdx.y * 64;
    const int n0  = blockIdx.x * 64;
    const int tid = threadIdx.x;
    const int ty  = tid >> 4;       // 0..15
    const int tx  = tid & 15;       // 0..15

    float acc[4][4] = {};

    for (int k0 = 0; k0 < K_; k0 += 16) {
        #pragma unroll
        for (int i = 0; i < 4; i++) {
            int idx = tid + i * 256;
            int row = idx >> 4;     // 0..63
            int kk  = idx & 15;     // 0..15
            As[kk][row] = A[(size_t)(m0 + row) * lda + k0 + kk];
            int ncol = n0 + row;
            Bs[kk][row] = (ncol < N_) ? W[(size_t)ncol * ldw + k0 + kk] : 0.f;
        }
        __syncthreads();
        #pragma unroll
        for (int kk = 0; kk < 16; kk++) {
            float a[4], bb[4];
            #pragma unroll
            for (int i = 0; i < 4; i++) a[i]  = As[kk][ty * 4 + i];
            #pragma unroll
            for (int j = 0; j < 4; j++) bb[j] = Bs[kk][tx * 4 + j];
            #pragma unroll
            for (int i = 0; i < 4; i++)
                #pragma unroll
                for (int j = 0; j < 4; j++)
                    acc[i][j] = fmaf(a[i], bb[j], acc[i][j]);
        }
        __syncthreads();
    }

    #pragma unroll
    for (int i = 0; i < 4; i++) {
        const int m = m0 + ty * 4 + i;
        #pragma unroll
        for (int j = 0; j < 4; j++) {
            const int n = n0 + tx * 4 + j;
            if (n < N_) {
                float v = acc[i][j] + bias[n];
                if constexpr (MODE == 1) {
                    v = fmaxf(v, 0.f);
                } else if constexpr (MODE == 2) {
                    v += extra[(size_t)m * eld + n];
                } else if constexpr (MODE == 3) {
                    float wv   = extra[(size_t)m * eld];
                    float prev = INIT ? 0.f : C[(size_t)m * ldc + n];
                    v = prev + wv * v;
                }
                C[(size_t)m * ldc + n] = v;
            }
        }
    }
}

// ---------------- flash attention (fp32, BQ=32, BK=64, 128 threads) ----------------
constexpr int BQ = 32;
constexpr int BK = 64;
constexpr int ATT_THREADS = 128;
constexpr int NSLOT = (BQ * DH + ATT_THREADS - 1) / ATT_THREADS;  // 17

__global__ void attn_kernel(const float* __restrict__ q,
                            const float* __restrict__ k,
                            const float* __restrict__ v,
                            float* __restrict__ o) {
    __shared__ float Qs[BQ][DH];
    __shared__ float KVs[BK][DH];
    __shared__ float Ps[BQ][BK];
    __shared__ float m_sm[BQ], l_sm[BQ], a_sm[BQ];

    const int tid = threadIdx.x;
    const int b   = blockIdx.z;
    const int hh  = blockIdx.y;
    const int q0  = blockIdx.x * BQ;
    const size_t base = (size_t)b * S * D + (size_t)hh * DH;

    if (tid < BQ) { m_sm[tid] = -INFINITY; l_sm[tid] = 0.f; }

    for (int idx = tid; idx < BQ * DH; idx += ATT_THREADS) {
        int qq = idx / DH, d = idx - qq * DH;
        Qs[qq][d] = q[base + (size_t)(q0 + qq) * D + d];
    }

    float oacc[NSLOT];
    int   sq[NSLOT], sd[NSLOT];
    #pragma unroll
    for (int i = 0; i < NSLOT; i++) {
        int idx = tid + i * ATT_THREADS;
        if (idx < BQ * DH) { sq[i] = idx / DH; sd[i] = idx - sq[i] * DH; }
        else               { sq[i] = -1;       sd[i] = 0; }
        oacc[i] = 0.f;
    }
    __syncthreads();

    const int ty = tid >> 4;   // 0..7 -> 4 query rows each
    const int tx = tid & 15;   // 0..15 -> 4 key cols each
    const float scale = rsqrtf((float)DH);

    for (int k0 = 0; k0 < S; k0 += BK) {
        // load K tile
        for (int idx = tid; idx < BK * DH; idx += ATT_THREADS) {
            int kk = idx / DH, d = idx - kk * DH;
            KVs[kk][d] = k[base + (size_t)(k0 + kk) * D + d];
        }
        __syncthreads();

        // scores 32x64 (each thread 4x4)
        float sc[4][4] = {};
        for (int d = 0; d < DH; d++) {
            float aq[4], bk_[4];
            #pragma unroll
            for (int i = 0; i < 4; i++) aq[i]  = Qs[ty * 4 + i][d];
            #pragma unroll
            for (int j = 0; j < 4; j++) bk_[j] = KVs[tx * 4 + j][d];
            #pragma unroll
            for (int i = 0; i < 4; i++)
                #pragma unroll
                for (int j = 0; j < 4; j++)
                    sc[i][j] = fmaf(aq[i], bk_[j], sc[i][j]);
        }

        // online softmax per query row
        #pragma unroll
        for (int i = 0; i < 4; i++) {
            const int qq = ty * 4 + i;
            float m_prev = m_sm[qq];
            float l_prev = l_sm[qq];
            float mx = -INFINITY;
            #pragma unroll
            for (int j = 0; j < 4; j++) { sc[i][j] *= scale; mx = fmaxf(mx, sc[i][j]); }
            #pragma unroll
            for (int off = 1; off < 16; off <<= 1)
                mx = fmaxf(mx, __shfl_xor_sync(0xffffffffu, mx, off));
            float m_new = fmaxf(m_prev, mx);
            float ps = 0.f;
            #pragma unroll
            for (int j = 0; j < 4; j++) {
                float p = __expf(sc[i][j] - m_new);
                Ps[qq][tx * 4 + j] = p;
                ps += p;
            }
            #pragma unroll
            for (int off = 1; off < 16; off <<= 1)
                ps += __shfl_xor_sync(0xffffffffu, ps, off);
            if (tx == 0) {
                float alpha = __expf(m_prev - m_new);
                a_sm[qq] = alpha;
                l_sm[qq] = l_prev * alpha + ps;
                m_sm[qq] = m_new;
            }
        }
        __syncthreads();

        // load V tile (overwrite KVs)
        for (int idx = tid; idx < BK * DH; idx += ATT_THREADS) {
            int kk = idx / DH, d = idx - kk * DH;
            KVs[kk][d] = v[base + (size_t)(k0 + kk) * D + d];
        }
        __syncthreads();

        // O += P * V (with rescale)
        #pragma unroll
        for (int i = 0; i < NSLOT; i++) {
            if (sq[i] >= 0) {
                float a   = a_sm[sq[i]];
                float acc = oacc[i] * a;
                #pragma unroll 4
                for (int kk = 0; kk < BK; kk++)
                    acc = fmaf(Ps[sq[i]][kk], KVs[kk][sd[i]], acc);
                oacc[i] = acc;
            }
        }
        __syncthreads();
    }

    #pragma unroll
    for (int i = 0; i < NSLOT; i++) {
        if (sq[i] >= 0)
            o[base + (size_t)(q0 + sq[i]) * D + sd[i]] = oacc[i] / l_sm[sq[i]];
    }
}

// ---------------- launcher ----------------
extern "C" void kernel_launch(void* const* d_in, const int* in_sizes, int n_in,
                              void* d_out, int out_size) {
    const float* x    = (const float*)d_in[0];
    const float* cond = (const float*)d_in[1];
    const float* Wq   = (const float*)d_in[2];
    const float* bq   = (const float*)d_in[3];
    const float* Wv   = (const float*)d_in[4];
    const float* bv   = (const float*)d_in[5];
    const float* Wk   = (const float*)d_in[6];
    const float* bk   = (const float*)d_in[7];
    const float* Wo   = (const float*)d_in[8];
    const float* bo   = (const float*)d_in[9];
    const float* g1   = (const float*)d_in[10];
    const float* bn1  = (const float*)d_in[11];
    const float* g2   = (const float*)d_in[12];
    const float* bn2  = (const float*)d_in[13];
    const float* Wf1  = (const float*)d_in[14];
    const float* bf1  = (const float*)d_in[15];
    const float* Wf2  = (const float*)d_in[16];
    const float* bf2  = (const float*)d_in[17];
    float* out = (float*)d_out;

    float* scratch = nullptr;
    cudaGetSymbolAddress((void**)&scratch, g_scratch);
    float* xc = scratch + OFF_XC;
    float* qb = scratch + OFF_Q;
    float* vb = scratch + OFF_V;
    float* kb = scratch + OFF_K;
    float* ob = scratch + OFF_O;
    float* hb = scratch + OFF_H;
    float* ff = scratch + OFF_FF;
    float* yb = scratch + OFF_Y;

    // 1. LN + concat
    ln_concat_kernel<<<MT, 256>>>(x, cond, g1, bn1, xc);

    const dim3 gD((D + 63) / 64, MT / 64);     // N = 1040
    const dim3 gE((E + 63) / 64, MT / 64);     // N = 1024
    const dim3 gF((DFF + 63) / 64, MT / 64);   // N = 4096

    // 2. Q, V projections
    sgemm_kernel<0, false><<<gD, 256>>>(xc, D, Wq, D, bq, qb, D, D, D, nullptr, 0);
    sgemm_kernel<0, false><<<gD, 256>>>(xc, D, Wv, D, bv, vb, D, D, D, nullptr, 0);

    // 3. conditioned K: k = sum_c w[:,c] * (xc @ Wk[c]^T + bk[c])
    sgemm_kernel<3, true><<<gD, 256>>>(xc, D, Wk, D, bk, kb, D, D, D, cond, CS);
    for (int c = 1; c < NC; c++) {
        sgemm_kernel<3, false><<<gD, 256>>>(xc, D, Wk + (size_t)c * D * D, D,
                                            bk + (size_t)c * D, kb, D, D, D,
                                            cond + c, CS);
    }

    // 4. attention
    attn_kernel<<<dim3(S / BQ, H, B), ATT_THREADS>>>(qb, kb, vb, ob);

    // 5. O-projection (only first E output cols needed) + residual xn
    sgemm_kernel<2, false><<<gE, 256>>>(ob, D, Wo, D, bo, hb, E, E, D, xc, D);

    // 6. FFN
    sgemm_kernel<1, false><<<gF, 256>>>(hb, E, Wf1, E, bf1, ff, DFF, DFF, E, nullptr, 0);
    sgemm_kernel<2, false><<<gE, 256>>>(ff, DFF, Wf2, DFF, bf2, yb, E, E, DFF, hb, E);

    // 7. final LN
    ln_final_kernel<<<MT, 256>>>(yb, g2, bn2, out);
}

// round 2
// speedup vs baseline: 2.9555x; 2.9555x over previous
#include <cuda_runtime.h>
#include <math.h>
#include <stdint.h>

// ---------------- problem constants ----------------
constexpr int B  = 4;
constexpr int S  = 2048;
constexpr int E  = 1024;
constexpr int CS = 16;
constexpr int NC = 8;
constexpr int H  = 16;
constexpr int D  = E + CS;      // 1040
constexpr int DH = D / H;       // 65
constexpr int DFF = 4 * E;      // 4096
constexpr int MT = B * S;       // 8192 tokens

// ---------------- scratch (static device memory, no allocs) ----------------
constexpr size_t XC_SZ = (size_t)MT * D;
constexpr size_t HE_SZ = (size_t)MT * E;
constexpr size_t FF_SZ = (size_t)MT * DFF;
constexpr size_t PS_SZ = (size_t)B * H * S * S;   // 268,435,456 floats (1.07 GB)

constexpr size_t OFF_XC = 0;
constexpr size_t OFF_Q  = OFF_XC + XC_SZ;
constexpr size_t OFF_V  = OFF_Q  + XC_SZ;
constexpr size_t OFF_K  = OFF_V  + XC_SZ;
constexpr size_t OFF_O  = OFF_K  + XC_SZ;
constexpr size_t OFF_H  = OFF_O  + XC_SZ;
constexpr size_t OFF_FF = OFF_H  + HE_SZ;
constexpr size_t OFF_Y  = OFF_FF + FF_SZ;
constexpr size_t OFF_PS = OFF_Y  + HE_SZ;
constexpr size_t SCRATCH_TOTAL = OFF_PS + PS_SZ;

__device__ float g_scratch[SCRATCH_TOTAL];

// ---------------- helpers ----------------
__device__ __forceinline__ uint32_t f2tf(float f) {
    uint32_t u;
    asm("cvt.rna.tf32.f32 %0, %1;" : "=r"(u) : "f"(f));
    return u;
}

__device__ __forceinline__ void mma_tf32(float* c, const uint32_t* a, const uint32_t* b) {
    asm volatile(
        "mma.sync.aligned.m16n8k8.row.col.f32.tf32.tf32.f32 "
        "{%0,%1,%2,%3}, {%4,%5,%6,%7}, {%8,%9}, {%0,%1,%2,%3};"
        : "+f"(c[0]), "+f"(c[1]), "+f"(c[2]), "+f"(c[3])
        : "r"(a[0]), "r"(a[1]), "r"(a[2]), "r"(a[3]), "r"(b[0]), "r"(b[1]));
}

__device__ __forceinline__ float blk_sum256(float v, float* red8) {
    #pragma unroll
    for (int o = 16; o > 0; o >>= 1) v += __shfl_xor_sync(0xffffffffu, v, o);
    __syncthreads();
    if ((threadIdx.x & 31) == 0) red8[threadIdx.x >> 5] = v;
    __syncthreads();
    if (threadIdx.x == 0) {
        float t = 0.f;
        #pragma unroll
        for (int i = 0; i < 8; i++) t += red8[i];
        red8[0] = t;
    }
    __syncthreads();
    return red8[0];
}

__device__ __forceinline__ float blk_max256(float v, float* red8) {
    #pragma unroll
    for (int o = 16; o > 0; o >>= 1) v = fmaxf(v, __shfl_xor_sync(0xffffffffu, v, o));
    __syncthreads();
    if ((threadIdx.x & 31) == 0) red8[threadIdx.x >> 5] = v;
    __syncthreads();
    if (threadIdx.x == 0) {
        float t = -INFINITY;
        #pragma unroll
        for (int i = 0; i < 8; i++) t = fmaxf(t, red8[i]);
        red8[0] = t;
    }
    __syncthreads();
    return red8[0];
}

// ---------------- LayerNorm(x) + concat conditioning -> xc ----------------
__global__ void ln_concat_kernel(const float* __restrict__ x,
                                 const float* __restrict__ cond,
                                 const float* __restrict__ g,
                                 const float* __restrict__ bta,
                                 float* __restrict__ xc) {
    __shared__ float red8[8];
    const int s   = blockIdx.x;
    const int tid = threadIdx.x;
    const float* xr = x + (size_t)s * E;
    float v0 = xr[tid], v1 = xr[tid + 256], v2 = xr[tid + 512], v3 = xr[tid + 768];
    float mean = blk_sum256(v0 + v1 + v2 + v3, red8) * (1.0f / E);
    float d0 = v0 - mean, d1 = v1 - mean, d2 = v2 - mean, d3 = v3 - mean;
    float var = blk_sum256(d0 * d0 + d1 * d1 + d2 * d2 + d3 * d3, red8) * (1.0f / E);
    float rstd = rsqrtf(var + 1e-5f);
    float* xo = xc + (size_t)s * D;
    xo[tid      ] = d0 * rstd * g[tid      ] + bta[tid      ];
    xo[tid + 256] = d1 * rstd * g[tid + 256] + bta[tid + 256];
    xo[tid + 512] = d2 * rstd * g[tid + 512] + bta[tid + 512];
    xo[tid + 768] = d3 * rstd * g[tid + 768] + bta[tid + 768];
    if (tid < CS) xo[E + tid] = cond[(size_t)s * CS + tid];
}

// ---------------- final LayerNorm ----------------
__global__ void ln_final_kernel(const float* __restrict__ y,
                                const float* __restrict__ g,
                                const float* __restrict__ bta,
                                float* __restrict__ out) {
    __shared__ float red8[8];
    const int s   = blockIdx.x;
    const int tid = threadIdx.x;
    const float* yr = y + (size_t)s * E;
    float v0 = yr[tid], v1 = yr[tid + 256], v2 = yr[tid + 512], v3 = yr[tid + 768];
    float mean = blk_sum256(v0 + v1 + v2 + v3, red8) * (1.0f / E);
    float d0 = v0 - mean, d1 = v1 - mean, d2 = v2 - mean, d3 = v3 - mean;
    float var = blk_sum256(d0 * d0 + d1 * d1 + d2 * d2 + d3 * d3, red8) * (1.0f / E);
    float rstd = rsqrtf(var + 1e-5f);
    float* o = out + (size_t)s * E;
    o[tid      ] = d0 * rstd * g[tid      ] + bta[tid      ];
    o[tid + 256] = d1 * rstd * g[tid + 256] + bta[tid + 256];
    o[tid + 512] = d2 * rstd * g[tid + 512] + bta[tid + 512];
    o[tid + 768] = d3 * rstd * g[tid + 768] + bta[tid + 768];
}

// ---------------- tf32 tensor-core GEMM ----------------
// C = A(M x K_) * B^T where (non-TRANSB) B = W stored N x K_ row-major,
// or (TRANSB) B[k][n] = W[k*ldw + n] (K_ x N row-major).
// MODE 0: C = acc + bias
// MODE 1: C = relu(acc + bias)
// MODE 2: C = acc + bias + extra[m*eld + n]
// MODE 3: C = (INIT?0:C) + extra[m*eld] * (acc + bias)
// MODE 4: C = acc * scale
// MODE 5: C = acc
// Batch: offset = (z>>4)*S1 + (z&15)*S2 per operand.
template <int MODE, bool INIT, bool TRANSB>
__global__ __launch_bounds__(256, 2)
void mma_gemm(const float* __restrict__ A, int lda,
              const float* __restrict__ W, int ldw,
              const float* __restrict__ bias,
              float* __restrict__ C, int ldc,
              int N_, int K_,
              const float* __restrict__ extra, int eld,
              float scale,
              long long aS1, long long aS2,
              long long wS1, long long wS2,
              long long cS1, long long cS2) {
    __shared__ float As[16][136];
    __shared__ float Bs[16][136];

    const int z  = blockIdx.z;
    const int zb = z >> 4, zh = z & 15;
    const float* Ab = A + (size_t)zb * aS1 + (size_t)zh * aS2;
    const float* Wb = W + (size_t)zb * wS1 + (size_t)zh * wS2;
    float*       Cb = C + (size_t)zb * cS1 + (size_t)zh * cS2;

    const int m0  = blockIdx.y * 128;
    const int n0  = blockIdx.x * 128;
    const int tid = threadIdx.x;
    const int warp = tid >> 5;
    const int lane = tid & 31;
    const int gid  = lane >> 2;   // 0..7
    const int tig  = lane & 3;    // 0..3
    const int wm = warp & 1;      // 2 warps along M (64 rows each)
    const int wn = warp >> 1;     // 4 warps along N (32 cols each)

    float acc[4][4][4];
    #pragma unroll
    for (int i = 0; i < 4; i++)
        #pragma unroll
        for (int j = 0; j < 4; j++)
            #pragma unroll
            for (int r = 0; r < 4; r++) acc[i][j][r] = 0.f;

    for (int k0 = 0; k0 < K_; k0 += 16) {
        // ---- stage A: [k][m] layout, swizzled, tf32-converted ----
        #pragma unroll
        for (int i = 0; i < 2; i++) {
            int idx = tid + i * 256;          // 0..511
            int m   = idx >> 2;               // 0..127
            int kg  = (idx & 3) * 4;          // 0,4,8,12
            const float* src = Ab + (size_t)(m0 + m) * lda + k0 + kg;
            const int sw = ((kg >> 2) & 3) << 3;
            #pragma unroll
            for (int j = 0; j < 4; j++) {
                float v = (k0 + kg + j < K_) ? src[j] : 0.f;
                As[kg + j][m ^ sw] = __uint_as_float(f2tf(v));
            }
        }
        // ---- stage B ----
        if constexpr (!TRANSB) {
            #pragma unroll
            for (int i = 0; i < 2; i++) {
                int idx = tid + i * 256;
                int n   = idx >> 2;
                int kg  = (idx & 3) * 4;
                const float* src = Wb + (size_t)(n0 + n) * ldw + k0 + kg;
                const bool nok = (n0 + n) < N_;
                const int sw = ((kg >> 2) & 3) << 3;
                #pragma unroll
                for (int j = 0; j < 4; j++) {
                    float v = (nok && (k0 + kg + j < K_)) ? src[j] : 0.f;
                    Bs[kg + j][n ^ sw] = __uint_as_float(f2tf(v));
                }
            }
        } else {
            #pragma unroll
            for (int i = 0; i < 2; i++) {
                int idx = tid + i * 256;
                int k   = idx >> 5;           // 0..15
                int ng  = (idx & 31) * 4;     // 0..124
                const float* src = Wb + (size_t)(k0 + k) * ldw + n0 + ng;
                const bool kok = (k0 + k) < K_;
                const int sw = ((k >> 2) & 3) << 3;
                #pragma unroll
                for (int j = 0; j < 4; j++) {
                    int n = ng + j;
                    float v = (kok && (n0 + n) < N_) ? src[j] : 0.f;
                    Bs[k][n ^ sw] = __uint_as_float(f2tf(v));
                }
            }
        }
        __syncthreads();

        // ---- compute ----
        #pragma unroll
        for (int kb = 0; kb < 16; kb += 8) {
            const int ka = kb + tig;
            const int kc = kb + tig + 4;
            const int sa = ((ka >> 2) & 3) << 3;
            const int sc = ((kc >> 2) & 3) << 3;
            uint32_t af[4][4], bf[4][2];
            #pragma unroll
            for (int ms = 0; ms < 4; ms++) {
                int mcol = wm * 64 + ms * 16 + gid;
                af[ms][0] = __float_as_uint(As[ka][mcol ^ sa]);
                af[ms][1] = __float_as_uint(As[ka][(mcol + 8) ^ sa]);
                af[ms][2] = __float_as_uint(As[kc][mcol ^ sc]);
                af[ms][3] = __float_as_uint(As[kc][(mcol + 8) ^ sc]);
            }
            #pragma unroll
            for (int ns = 0; ns < 4; ns++) {
                int ncol = wn * 32 + ns * 8 + gid;
                bf[ns][0] = __float_as_uint(Bs[ka][ncol ^ sa]);
                bf[ns][1] = __float_as_uint(Bs[kc][ncol ^ sc]);
            }
            #pragma unroll
            for (int ms = 0; ms < 4; ms++)
                #pragma unroll
                for (int ns = 0; ns < 4; ns++)
                    mma_tf32(acc[ms][ns], af[ms], bf[ns]);
        }
        __syncthreads();
    }

    // ---- epilogue ----
    #pragma unroll
    for (int ms = 0; ms < 4; ms++) {
        #pragma unroll
        for (int ns = 0; ns < 4; ns++) {
            #pragma unroll
            for (int r = 0; r < 4; r++) {
                const int row = m0 + wm * 64 + ms * 16 + gid + ((r >> 1) * 8);
                const int col = n0 + wn * 32 + ns * 8 + tig * 2 + (r & 1);
                if (col < N_) {
                    float v = acc[ms][ns][r];
                    if constexpr (MODE == 0) {
                        v += bias[col];
                    } else if constexpr (MODE == 1) {
                        v = fmaxf(v + bias[col], 0.f);
                    } else if constexpr (MODE == 2) {
                        v += bias[col] + extra[(size_t)row * eld + col];
                    } else if constexpr (MODE == 3) {
                        float wv = extra[(size_t)row * eld];
                        float prev = INIT ? 0.f : Cb[(size_t)row * ldc + col];
                        v = prev + wv * (v + bias[col]);
                    } else if constexpr (MODE == 4) {
                        v *= scale;
                    }
                    Cb[(size_t)row * ldc + col] = v;
                }
            }
        }
    }
}

// ---------------- row softmax over S=2048 columns ----------------
__global__ void softmax_rows(float* __restrict__ P) {
    __shared__ float red8[8];
    float* row = P + (size_t)blockIdx.x * S;
    const int tid = threadIdx.x;
    float4 v0 = ((float4*)row)[tid];
    float4 v1 = ((float4*)row)[tid + 256];
    float mx = fmaxf(fmaxf(fmaxf(v0.x, v0.y), fmaxf(v0.z, v0.w)),
                     fmaxf(fmaxf(v1.x, v1.y), fmaxf(v1.z, v1.w)));
    mx = blk_max256(mx, red8);
    v0.x = __expf(v0.x - mx); v0.y = __expf(v0.y - mx);
    v0.z = __expf(v0.z - mx); v0.w = __expf(v0.w - mx);
    v1.x = __expf(v1.x - mx); v1.y = __expf(v1.y - mx);
    v1.z = __expf(v1.z - mx); v1.w = __expf(v1.w - mx);
    float sum = v0.x + v0.y + v0.z + v0.w + v1.x + v1.y + v1.z + v1.w;
    sum = blk_sum256(sum, red8);
    float inv = 1.0f / sum;
    v0.x *= inv; v0.y *= inv; v0.z *= inv; v0.w *= inv;
    v1.x *= inv; v1.y *= inv; v1.z *= inv; v1.w *= inv;
    ((float4*)row)[tid] = v0;
    ((float4*)row)[tid + 256] = v1;
}

// ---------------- launcher ----------------
extern "C" void kernel_launch(void* const* d_in, const int* in_sizes, int n_in,
                              void* d_out, int out_size) {
    const float* x    = (const float*)d_in[0];
    const float* cond = (const float*)d_in[1];
    const float* Wq   = (const float*)d_in[2];
    const float* bq   = (const float*)d_in[3];
    const float* Wv   = (const float*)d_in[4];
    const float* bv   = (const float*)d_in[5];
    const float* Wk   = (const float*)d_in[6];
    const float* bk   = (const float*)d_in[7];
    const float* Wo   = (const float*)d_in[8];
    const float* bo   = (const float*)d_in[9];
    const float* g1   = (const float*)d_in[10];
    const float* bn1  = (const float*)d_in[11];
    const float* g2   = (const float*)d_in[12];
    const float* bn2  = (const float*)d_in[13];
    const float* Wf1  = (const float*)d_in[14];
    const float* bf1  = (const float*)d_in[15];
    const float* Wf2  = (const float*)d_in[16];
    const float* bf2  = (const float*)d_in[17];
    float* out = (float*)d_out;

    float* scratch = nullptr;
    cudaGetSymbolAddress((void**)&scratch, g_scratch);
    float* xc = scratch + OFF_XC;
    float* qb = scratch + OFF_Q;
    float* vb = scratch + OFF_V;
    float* kb_ = scratch + OFF_K;
    float* ob = scratch + OFF_O;
    float* hb = scratch + OFF_H;
    float* ff = scratch + OFF_FF;
    float* yb = scratch + OFF_Y;
    float* ps = scratch + OFF_PS;

    const float attn_scale = 1.0f / sqrtf((float)DH);

    // 1. LN + concat
    ln_concat_kernel<<<MT, 256>>>(x, cond, g1, bn1, xc);

    const dim3 gD((D + 127) / 128, MT / 128);     // 9 x 64
    const dim3 gE((E + 127) / 128, MT / 128);     // 8 x 64
    const dim3 gF((DFF + 127) / 128, MT / 128);   // 32 x 64

    // 2. Q, V projections
    mma_gemm<0, false, false><<<gD, 256>>>(xc, D, Wq, D, bq, qb, D, D, D,
                                           nullptr, 0, 0.f, 0,0,0,0,0,0);
    mma_gemm<0, false, false><<<gD, 256>>>(xc, D, Wv, D, bv, vb, D, D, D,
                                           nullptr, 0, 0.f, 0,0,0,0,0,0);

    // 3. conditioned K
    mma_gemm<3, true, false><<<gD, 256>>>(xc, D, Wk, D, bk, kb_, D, D, D,
                                          cond, CS, 0.f, 0,0,0,0,0,0);
    for (int c = 1; c < NC; c++) {
        mma_gemm<3, false, false><<<gD, 256>>>(xc, D, Wk + (size_t)c * D * D, D,
                                               bk + (size_t)c * D, kb_, D, D, D,
                                               cond + c, CS, 0.f, 0,0,0,0,0,0);
    }

    // 4a. scores = scale * Q K^T   (batched over B*H = 64)
    {
        dim3 g(S / 128, S / 128, B * H);
        mma_gemm<4, false, false><<<g, 256>>>(
            qb, D, kb_, D, nullptr, ps, S, S, DH,
            nullptr, 0, attn_scale,
            (long long)S * D, (long long)DH,
            (long long)S * D, (long long)DH,
            (long long)H * S * S, (long long)S * S);
    }
    // 4b. softmax
    softmax_rows<<<B * H * S, 256>>>(ps);
    // 4c. O = P V   (trans-B batched)
    {
        dim3 g(1, S / 128, B * H);
        mma_gemm<5, false, true><<<g, 256>>>(
            ps, S, vb, D, nullptr, ob, D, DH, S,
            nullptr, 0, 0.f,
            (long long)H * S * S, (long long)S * S,
            (long long)S * D, (long long)DH,
            (long long)S * D, (long long)DH);
    }

    // 5. O-projection (first E cols only) + residual xn
    mma_gemm<2, false, false><<<gE, 256>>>(ob, D, Wo, D, bo, hb, E, E, D,
                                           xc, D, 0.f, 0,0,0,0,0,0);

    // 6. FFN
    mma_gemm<1, false, false><<<gF, 256>>>(hb, E, Wf1, E, bf1, ff, DFF, DFF, E,
                                           nullptr, 0, 0.f, 0,0,0,0,0,0);
    mma_gemm<2, false, false><<<gE, 256>>>(ff, DFF, Wf2, DFF, bf2, yb, E, E, DFF,
                                           hb, E, 0.f, 0,0,0,0,0,0);

    // 7. final LN
    ln_final_kernel<<<MT, 256>>>(yb, g2, bn2, out);
}

// round 3
// speedup vs baseline: 4.9339x; 1.6694x over previous
#include <cuda_runtime.h>
#include <math.h>
#include <stdint.h>

// ---------------- problem constants ----------------
constexpr int B  = 4;
constexpr int S  = 2048;
constexpr int E  = 1024;
constexpr int CS = 16;
constexpr int NC = 8;
constexpr int H  = 16;
constexpr int D  = E + CS;      // 1040
constexpr int DH = D / H;       // 65
constexpr int DHP = 80;         // padded head dim (mult of 16)
constexpr int DFF = 4 * E;      // 4096
constexpr int MT = B * S;       // 8192

// ---------------- scratch ----------------
constexpr size_t XC_SZ = (size_t)MT * D;
constexpr size_t HP_SZ = (size_t)B * H * S * DHP;  // 10,485,760
constexpr size_t HE_SZ = (size_t)MT * E;
constexpr size_t FF_SZ = (size_t)MT * DFF;
constexpr size_t PS_SZ = (size_t)B * H * S * S;
constexpr size_t AP_SZ = (size_t)MT * (NC * D);    // 68,157,440

constexpr size_t OFF_XC  = 0;
constexpr size_t OFF_QP  = OFF_XC  + XC_SZ;
constexpr size_t OFF_KP  = OFF_QP  + HP_SZ;
constexpr size_t OFF_VP  = OFF_KP  + HP_SZ;
constexpr size_t OFF_OB  = OFF_VP  + HP_SZ;
constexpr size_t OFF_HB  = OFF_OB  + XC_SZ;
constexpr size_t OFF_FF  = OFF_HB  + HE_SZ;
constexpr size_t OFF_YB  = OFF_FF  + FF_SZ;
constexpr size_t OFF_PS  = OFF_YB  + HE_SZ;
constexpr size_t OFF_AP  = OFF_PS  + PS_SZ;
constexpr size_t OFF_WQ  = OFF_AP  + AP_SZ;
constexpr size_t OFF_WV  = OFF_WQ  + (size_t)D * D;
constexpr size_t OFF_WO  = OFF_WV  + (size_t)D * D;
constexpr size_t OFF_WK  = OFF_WO  + (size_t)D * D;
constexpr size_t OFF_WF1 = OFF_WK  + (size_t)NC * D * D;
constexpr size_t OFF_WF2 = OFF_WF1 + (size_t)DFF * E;
constexpr size_t SCRATCH_TOTAL = OFF_WF2 + (size_t)E * DFF;

__device__ float g_scratch[SCRATCH_TOTAL];

// ---------------- helpers ----------------
__device__ __forceinline__ float f2tf_f(float f) {
    uint32_t u;
    asm("cvt.rna.tf32.f32 %0, %1;" : "=r"(u) : "f"(f));
    return __uint_as_float(u);
}

__device__ __forceinline__ void mma_tf32(float* c, const uint32_t* a, const uint32_t* b) {
    asm volatile(
        "mma.sync.aligned.m16n8k8.row.col.f32.tf32.tf32.f32 "
        "{%0,%1,%2,%3}, {%4,%5,%6,%7}, {%8,%9}, {%0,%1,%2,%3};"
        : "+f"(c[0]), "+f"(c[1]), "+f"(c[2]), "+f"(c[3])
        : "r"(a[0]), "r"(a[1]), "r"(a[2]), "r"(a[3]), "r"(b[0]), "r"(b[1]));
}

__device__ __forceinline__ void cp16(uint32_t dst, const float* src, int sz) {
    asm volatile("cp.async.cg.shared.global [%0], [%1], 16, %2;"
                 :: "r"(dst), "l"(src), "r"(sz));
}

__device__ __forceinline__ float blk_sum256(float v, float* red8) {
    #pragma unroll
    for (int o = 16; o > 0; o >>= 1) v += __shfl_xor_sync(0xffffffffu, v, o);
    __syncthreads();
    if ((threadIdx.x & 31) == 0) red8[threadIdx.x >> 5] = v;
    __syncthreads();
    if (threadIdx.x == 0) {
        float t = 0.f;
        #pragma unroll
        for (int i = 0; i < 8; i++) t += red8[i];
        red8[0] = t;
    }
    __syncthreads();
    return red8[0];
}

__device__ __forceinline__ float blk_max256(float v, float* red8) {
    #pragma unroll
    for (int o = 16; o > 0; o >>= 1) v = fmaxf(v, __shfl_xor_sync(0xffffffffu, v, o));
    __syncthreads();
    if ((threadIdx.x & 31) == 0) red8[threadIdx.x >> 5] = v;
    __syncthreads();
    if (threadIdx.x == 0) {
        float t = -INFINITY;
        #pragma unroll
        for (int i = 0; i < 8; i++) t = fmaxf(t, red8[i]);
        red8[0] = t;
    }
    __syncthreads();
    return red8[0];
}

// ---------------- tf32 rounding copy (weights) ----------------
__global__ void cvt_tf32_kernel(const float* __restrict__ src, float* __restrict__ dst, int n4) {
    int i = blockIdx.x * blockDim.x + threadIdx.x;
    if (i < n4) {
        float4 v = ((const float4*)src)[i];
        v.x = f2tf_f(v.x); v.y = f2tf_f(v.y); v.z = f2tf_f(v.z); v.w = f2tf_f(v.w);
        ((float4*)dst)[i] = v;
    }
}

// ---------------- LayerNorm + concat (stores tf32-rounded) ----------------
__global__ void ln_concat_kernel(const float* __restrict__ x,
                                 const float* __restrict__ cond,
                                 const float* __restrict__ g,
                                 const float* __restrict__ bta,
                                 float* __restrict__ xc) {
    __shared__ float red8[8];
    const int s   = blockIdx.x;
    const int tid = threadIdx.x;
    const float* xr = x + (size_t)s * E;
    float v0 = xr[tid], v1 = xr[tid + 256], v2 = xr[tid + 512], v3 = xr[tid + 768];
    float mean = blk_sum256(v0 + v1 + v2 + v3, red8) * (1.0f / E);
    float d0 = v0 - mean, d1 = v1 - mean, d2 = v2 - mean, d3 = v3 - mean;
    float var = blk_sum256(d0 * d0 + d1 * d1 + d2 * d2 + d3 * d3, red8) * (1.0f / E);
    float rstd = rsqrtf(var + 1e-5f);
    float* xo = xc + (size_t)s * D;
    xo[tid      ] = f2tf_f(d0 * rstd * g[tid      ] + bta[tid      ]);
    xo[tid + 256] = f2tf_f(d1 * rstd * g[tid + 256] + bta[tid + 256]);
    xo[tid + 512] = f2tf_f(d2 * rstd * g[tid + 512] + bta[tid + 512]);
    xo[tid + 768] = f2tf_f(d3 * rstd * g[tid + 768] + bta[tid + 768]);
    if (tid < CS) xo[E + tid] = f2tf_f(cond[(size_t)s * CS + tid]);
}

// ---------------- final LayerNorm ----------------
__global__ void ln_final_kernel(const float* __restrict__ y,
                                const float* __restrict__ g,
                                const float* __restrict__ bta,
                                float* __restrict__ out) {
    __shared__ float red8[8];
    const int s   = blockIdx.x;
    const int tid = threadIdx.x;
    const float* yr = y + (size_t)s * E;
    float v0 = yr[tid], v1 = yr[tid + 256], v2 = yr[tid + 512], v3 = yr[tid + 768];
    float mean = blk_sum256(v0 + v1 + v2 + v3, red8) * (1.0f / E);
    float d0 = v0 - mean, d1 = v1 - mean, d2 = v2 - mean, d3 = v3 - mean;
    float var = blk_sum256(d0 * d0 + d1 * d1 + d2 * d2 + d3 * d3, red8) * (1.0f / E);
    float rstd = rsqrtf(var + 1e-5f);
    float* o = out + (size_t)s * E;
    o[tid      ] = d0 * rstd * g[tid      ] + bta[tid      ];
    o[tid + 256] = d1 * rstd * g[tid + 256] + bta[tid + 256];
    o[tid + 512] = d2 * rstd * g[tid + 512] + bta[tid + 512];
    o[tid + 768] = d3 * rstd * g[tid + 768] + bta[tid + 768];
}

// ---------------- build A' = w[m,c] * xc[m,d], tf32-rounded ----------------
__global__ void build_ap_kernel(const float* __restrict__ xc,
                                const float* __restrict__ cond,
                                float* __restrict__ ap) {
    __shared__ float xrow[D];
    __shared__ float w8[NC];
    const int m   = blockIdx.x;
    const int tid = threadIdx.x;
    if (tid < NC) w8[tid] = cond[(size_t)m * CS + tid];
    for (int d = tid; d < D; d += 256) xrow[d] = xc[(size_t)m * D + d];
    __syncthreads();
    float* apr = ap + (size_t)m * (NC * D);
    #pragma unroll
    for (int c = 0; c < NC; c++) {
        float w = w8[c];
        for (int d = tid; d < D; d += 256)
            apr[c * D + d] = f2tf_f(w * xrow[d]);
    }
}

// ---------------- row softmax (stores tf32-rounded) ----------------
__global__ void softmax_rows(float* __restrict__ P) {
    __shared__ float red8[8];
    float* row = P + (size_t)blockIdx.x * S;
    const int tid = threadIdx.x;
    float4 v0 = ((float4*)row)[tid];
    float4 v1 = ((float4*)row)[tid + 256];
    float mx = fmaxf(fmaxf(fmaxf(v0.x, v0.y), fmaxf(v0.z, v0.w)),
                     fmaxf(fmaxf(v1.x, v1.y), fmaxf(v1.z, v1.w)));
    mx = blk_max256(mx, red8);
    v0.x = __expf(v0.x - mx); v0.y = __expf(v0.y - mx);
    v0.z = __expf(v0.z - mx); v0.w = __expf(v0.w - mx);
    v1.x = __expf(v1.x - mx); v1.y = __expf(v1.y - mx);
    v1.z = __expf(v1.z - mx); v1.w = __expf(v1.w - mx);
    float sum = v0.x + v0.y + v0.z + v0.w + v1.x + v1.y + v1.z + v1.w;
    sum = blk_sum256(sum, red8);
    float inv = 1.0f / sum;
    v0.x = f2tf_f(v0.x * inv); v0.y = f2tf_f(v0.y * inv);
    v0.z = f2tf_f(v0.z * inv); v0.w = f2tf_f(v0.w * inv);
    v1.x = f2tf_f(v1.x * inv); v1.y = f2tf_f(v1.y * inv);
    v1.z = f2tf_f(v1.z * inv); v1.w = f2tf_f(v1.w * inv);
    ((float4*)row)[tid] = v0;
    ((float4*)row)[tid + 256] = v1;
}

// ---------------- tf32 GEMM, cp.async double-buffered ----------------
// C = A(MxK) * B^T. Inputs must already be tf32-rounded.
// MODE: 0 +bias | 1 relu(+bias) | 2 +bias+extra | 4 *scale | 5 plain | 6 +sum_c w*bk
// SCAT: scatter output to [B,H,S,DHP] padded layout (row->(b,s), col->(h,dh))
// TRANSB: B stored [K][N] row-major (ldw = row stride)
// SEGB: B is segmented: W[n][k] = Wseg[(k/segLen)*segStride + n*ldw + k%segLen]
// ROUND: tf32-round before store
template <int MODE, bool SCAT, bool TRANSB, bool SEGB, bool ROUND>
__global__ __launch_bounds__(256, 2)
void mma_gemm(const float* __restrict__ A, int lda,
              const float* __restrict__ W, int ldw,
              const float* __restrict__ bias,
              float* __restrict__ C, int ldc,
              int N_, int K_, int Nsrc,
              const float* __restrict__ extra, int eld, float scale,
              long long aS1, long long aS2,
              long long wS1, long long wS2,
              long long cS1, long long cS2,
              int segLen, long long segStride) {
    __shared__ __align__(16) float As[2][128][20];
    __shared__ __align__(16) float Bs[2][128][20];   // TRANSB reinterpreted as [2][16][136]

    const int z  = blockIdx.z;
    const int zb = z >> 4, zh = z & 15;
    const float* Ab = A + (size_t)zb * aS1 + (size_t)zh * aS2;
    const float* Wb = W + (size_t)zb * wS1 + (size_t)zh * wS2;
    float*       Cb = C + (size_t)zb * cS1 + (size_t)zh * cS2;

    const int m0  = blockIdx.y * 128;
    const int n0  = blockIdx.x * 128;
    const int tid = threadIdx.x;
    const int warp = tid >> 5;
    const int lane = tid & 31;
    const int gid  = lane >> 2;
    const int tig  = lane & 3;
    const int wm = warp & 1;
    const int wn = warp >> 1;

    const uint32_t as_base = (uint32_t)__cvta_generic_to_shared(&As[0][0][0]);
    const uint32_t bs_base = (uint32_t)__cvta_generic_to_shared(&Bs[0][0][0]);

    float acc[4][4][4];
    #pragma unroll
    for (int i = 0; i < 4; i++)
        #pragma unroll
        for (int j = 0; j < 4; j++)
            #pragma unroll
            for (int r = 0; r < 4; r++) acc[i][j][r] = 0.f;

    // staging helpers
    auto stageAB = [&](int st, int k0) {
        #pragma unroll
        for (int i = 0; i < 2; i++) {
            int idx = tid + (i << 8);
            int m = idx >> 2, kg = (idx & 3) << 2;
            cp16(as_base + (uint32_t)((((st << 7) + m) * 20 + kg) << 2),
                 Ab + (size_t)(m0 + m) * lda + (k0 + kg), 16);
        }
        if constexpr (!TRANSB) {
            const float* Wc; int kl;
            if constexpr (SEGB) {
                int c = k0 / segLen;
                Wc = Wb + (size_t)c * segStride;
                kl = k0 - c * segLen;
            } else { Wc = Wb; kl = k0; }
            #pragma unroll
            for (int i = 0; i < 2; i++) {
                int idx = tid + (i << 8);
                int n = idx >> 2, kg = (idx & 3) << 2;
                cp16(bs_base + (uint32_t)((((st << 7) + n) * 20 + kg) << 2),
                     Wc + (size_t)(n0 + n) * ldw + (kl + kg),
                     (n0 + n) < Nsrc ? 16 : 0);
            }
        } else {
            #pragma unroll
            for (int i = 0; i < 2; i++) {
                int idx = tid + (i << 8);
                int k = idx >> 5, ng = (idx & 31) << 2;
                cp16(bs_base + (uint32_t)((((st << 4) + k) * 136 + ng) << 2),
                     Wb + (size_t)(k0 + k) * ldw + (n0 + ng),
                     (n0 + ng) < Nsrc ? 16 : 0);
            }
        }
    };

    stageAB(0, 0);
    asm volatile("cp.async.commit_group;");

    int st = 0;
    for (int k0 = 0; k0 < K_; k0 += 16) {
        if (k0 + 16 < K_) {
            stageAB(st ^ 1, k0 + 16);
            asm volatile("cp.async.commit_group;");
            asm volatile("cp.async.wait_group 1;");
        } else {
            asm volatile("cp.async.wait_group 0;");
        }
        __syncthreads();

        const float (*Am)[20]  = As[st];
        const float (*Bm)[20]  = Bs[st];
        const float (*Bt)[136] = (const float (*)[136])(&Bs[0][0][0] + (size_t)st * 16 * 136);

        #pragma unroll
        for (int kb = 0; kb < 16; kb += 8) {
            const int ka = kb + tig;
            const int kc = ka + 4;
            uint32_t af[4][4], bf[4][2];
            #pragma unroll
            for (int ms = 0; ms < 4; ms++) {
                int mcol = wm * 64 + ms * 16 + gid;
                af[ms][0] = __float_as_uint(Am[mcol][ka]);
                af[ms][1] = __float_as_uint(Am[mcol + 8][ka]);
                af[ms][2] = __float_as_uint(Am[mcol][kc]);
                af[ms][3] = __float_as_uint(Am[mcol + 8][kc]);
            }
            #pragma unroll
            for (int ns = 0; ns < 4; ns++) {
                int ncol = wn * 32 + ns * 8 + gid;
                if constexpr (TRANSB) {
                    bf[ns][0] = __float_as_uint(Bt[ka][ncol]);
                    bf[ns][1] = __float_as_uint(Bt[kc][ncol]);
                } else {
                    bf[ns][0] = __float_as_uint(Bm[ncol][ka]);
                    bf[ns][1] = __float_as_uint(Bm[ncol][kc]);
                }
            }
            #pragma unroll
            for (int ms = 0; ms < 4; ms++)
                #pragma unroll
                for (int ns = 0; ns < 4; ns++)
                    mma_tf32(acc[ms][ns], af[ms], bf[ns]);
        }
        __syncthreads();
        st ^= 1;
    }

    // ---- epilogue ----
    #pragma unroll
    for (int ms = 0; ms < 4; ms++) {
        #pragma unroll
        for (int ns = 0; ns < 4; ns++) {
            #pragma unroll
            for (int r = 0; r < 4; r++) {
                const int row = m0 + wm * 64 + ms * 16 + gid + ((r >> 1) * 8);
                const int col = n0 + wn * 32 + ns * 8 + tig * 2 + (r & 1);
                if (col < N_) {
                    float v = acc[ms][ns][r];
                    if constexpr (MODE == 0) {
                        v += bias[col];
                    } else if constexpr (MODE == 1) {
                        v = fmaxf(v + bias[col], 0.f);
                    } else if constexpr (MODE == 2) {
                        v += bias[col] + extra[(size_t)row * eld + col];
                    } else if constexpr (MODE == 4) {
                        v *= scale;
                    } else if constexpr (MODE == 6) {
                        const float* wrow = extra + (size_t)row * eld;
                        float bsum = 0.f;
                        #pragma unroll
                        for (int c = 0; c < NC; c++)
                            bsum += wrow[c] * bias[(size_t)c * D + col];
                        v += bsum;
                    }
                    if constexpr (ROUND) v = f2tf_f(v);
                    if constexpr (SCAT) {
                        int b = row >> 11, s = row & (S - 1);
                        int h = col / DH;
                        int dh = col - h * DH;
                        Cb[(((size_t)(b * H + h)) * S + s) * DHP + dh] = v;
                    } else {
                        Cb[(size_t)row * ldc + col] = v;
                    }
                }
            }
        }
    }
}

// ---------------- launcher ----------------
extern "C" void kernel_launch(void* const* d_in, const int* in_sizes, int n_in,
                              void* d_out, int out_size) {
    const float* x    = (const float*)d_in[0];
    const float* cond = (const float*)d_in[1];
    const float* Wq   = (const float*)d_in[2];
    const float* bq   = (const float*)d_in[3];
    const float* Wv   = (const float*)d_in[4];
    const float* bv   = (const float*)d_in[5];
    const float* Wk   = (const float*)d_in[6];
    const float* bk   = (const float*)d_in[7];
    const float* Wo   = (const float*)d_in[8];
    const float* bo   = (const float*)d_in[9];
    const float* g1   = (const float*)d_in[10];
    const float* bn1  = (const float*)d_in[11];
    const float* g2   = (const float*)d_in[12];
    const float* bn2  = (const float*)d_in[13];
    const float* Wf1  = (const float*)d_in[14];
    const float* bf1  = (const float*)d_in[15];
    const float* Wf2  = (const float*)d_in[16];
    const float* bf2  = (const float*)d_in[17];
    float* out = (float*)d_out;

    float* sc = nullptr;
    cudaGetSymbolAddress((void**)&sc, g_scratch);
    float* xc  = sc + OFF_XC;
    float* qp  = sc + OFF_QP;
    float* kp  = sc + OFF_KP;
    float* vp  = sc + OFF_VP;
    float* ob  = sc + OFF_OB;
    float* hb  = sc + OFF_HB;
    float* ff  = sc + OFF_FF;
    float* yb  = sc + OFF_YB;
    float* ps  = sc + OFF_PS;
    float* ap  = sc + OFF_AP;
    float* wqc = sc + OFF_WQ;
    float* wvc = sc + OFF_WV;
    float* woc = sc + OFF_WO;
    float* wkc = sc + OFF_WK;
    float* wf1c = sc + OFF_WF1;
    float* wf2c = sc + OFF_WF2;

    const float attn_scale = 1.0f / sqrtf((float)DH);

    // 0. round weights to tf32 once per call
    auto cvtw = [&](const float* src, float* dst, size_t n) {
        int n4 = (int)(n / 4);
        cvt_tf32_kernel<<<(n4 + 255) / 256, 256>>>(src, dst, n4);
    };
    cvtw(Wq, wqc, (size_t)D * D);
    cvtw(Wv, wvc, (size_t)D * D);
    cvtw(Wo, woc, (size_t)D * D);
    cvtw(Wk, wkc, (size_t)NC * D * D);
    cvtw(Wf1, wf1c, (size_t)DFF * E);
    cvtw(Wf2, wf2c, (size_t)E * DFF);

    // 1. LN + concat (rounded)
    ln_concat_kernel<<<MT, 256>>>(x, cond, g1, bn1, xc);

    // 2. A' = w * xc (rounded)
    build_ap_kernel<<<MT, 256>>>(xc, cond, ap);

    const dim3 gD((D + 127) / 128, MT / 128);     // 9 x 64
    const dim3 gE(E / 128, MT / 128);             // 8 x 64
    const dim3 gF(DFF / 128, MT / 128);           // 32 x 64

    // 3. Q, V projections -> padded [B,H,S,80] scatter
    mma_gemm<0, true, false, false, true><<<gD, 256>>>(
        xc, D, wqc, D, bq, qp, 0, D, D, D,
        nullptr, 0, 0.f, 0,0,0,0,0,0, 0, 0);
    mma_gemm<0, true, false, false, true><<<gD, 256>>>(
        xc, D, wvc, D, bv, vp, 0, D, D, D,
        nullptr, 0, 0.f, 0,0,0,0,0,0, 0, 0);

    // 4. conditioned K: single GEMM, K = 8320, segmented B over Wk[c]
    mma_gemm<6, true, false, true, true><<<gD, 256>>>(
        ap, NC * D, wkc, D, bk, kp, 0, D, NC * D, D,
        cond, CS, 0.f, 0,0,0,0,0,0, D, (long long)D * D);

    // 5a. scores = scale * Q K^T  (batched over B*H)
    {
        dim3 g(S / 128, S / 128, B * H);
        mma_gemm<4, false, false, false, false><<<g, 256>>>(
            qp, DHP, kp, DHP, nullptr, ps, S, S, DHP, S,
            nullptr, 0, attn_scale,
            (long long)H * S * DHP, (long long)S * DHP,
            (long long)H * S * DHP, (long long)S * DHP,
            (long long)H * S * S, (long long)S * S, 0, 0);
    }
    // 5b. softmax (stores rounded)
    softmax_rows<<<B * H * S, 256>>>(ps);
    // 5c. O = P V  (trans-B), scatter via strides into [B,S,D] at col h*65
    {
        dim3 g(1, S / 128, B * H);
        mma_gemm<5, false, true, false, true><<<g, 256>>>(
            ps, S, vp, DHP, nullptr, ob, D, DH, S, DHP,
            nullptr, 0, 0.f,
            (long long)H * S * S, (long long)S * S,
            (long long)H * S * DHP, (long long)S * DHP,
            (long long)S * D, (long long)DH, 0, 0);
    }

    // 6. O-projection (first E cols) + residual xn
    mma_gemm<2, false, false, false, true><<<gE, 256>>>(
        ob, D, woc, D, bo, hb, E, E, D, E,
        xc, D, 0.f, 0,0,0,0,0,0, 0, 0);

    // 7. FFN
    mma_gemm<1, false, false, false, true><<<gF, 256>>>(
        hb, E, wf1c, E, bf1, ff, DFF, DFF, E, DFF,
        nullptr, 0, 0.f, 0,0,0,0,0,0, 0, 0);
    mma_gemm<2, false, false, false, false><<<gE, 256>>>(
        ff, DFF, wf2c, DFF, bf2, yb, E, E, DFF, E,
        hb, E, 0.f, 0,0,0,0,0,0, 0, 0);

    // 8. final LN
    ln_final_kernel<<<MT, 256>>>(yb, g2, bn2, out);
}

// round 7
// speedup vs baseline: 8.8576x; 1.7953x over previous
#include <cuda_runtime.h>
#include <cuda_fp16.h>
#include <math.h>
#include <stdint.h>

// ---------------- problem constants ----------------
constexpr int B  = 4;
constexpr int S  = 2048;
constexpr int E  = 1024;
constexpr int CS = 16;
constexpr int NC = 8;
constexpr int H  = 16;
constexpr int D  = E + CS;      // 1040
constexpr int DH = D / H;       // 65
constexpr int DHP = 80;         // padded head dim
constexpr int DFF = 4 * E;      // 4096
constexpr int MT = B * S;       // 8192

// ---------------- arena (bytes) ----------------
constexpr size_t AL(size_t x) { return (x + 255) & ~(size_t)255; }
constexpr size_t SZ_XCH = (size_t)MT * D * 2;
constexpr size_t SZ_XNF = (size_t)MT * E * 4;
constexpr size_t SZ_HP  = (size_t)B * H * S * DHP * 2;
constexpr size_t SZ_PS  = (size_t)B * H * S * S * 2;
constexpr size_t SZ_OB  = (size_t)MT * D * 2;
constexpr size_t SZ_HBH = (size_t)MT * E * 2;
constexpr size_t SZ_HBF = (size_t)MT * E * 4;
constexpr size_t SZ_FF  = (size_t)MT * DFF * 2;
constexpr size_t SZ_YB  = (size_t)MT * E * 4;
constexpr size_t SZ_AP  = (size_t)MT * NC * D * 2;
constexpr size_t SZ_WDD = (size_t)D * D * 2;
constexpr size_t SZ_WK  = (size_t)NC * D * D * 2;
constexpr size_t SZ_WF  = (size_t)DFF * E * 2;

constexpr size_t O_XCH = 0;
constexpr size_t O_XNF = AL(O_XCH + SZ_XCH);
constexpr size_t O_QP  = AL(O_XNF + SZ_XNF);
constexpr size_t O_KP  = AL(O_QP  + SZ_HP);
constexpr size_t O_VT  = AL(O_KP  + SZ_HP);
constexpr size_t O_PS  = AL(O_VT  + SZ_HP);
constexpr size_t O_OB  = AL(O_PS  + SZ_PS);
constexpr size_t O_HBH = AL(O_OB  + SZ_OB);
constexpr size_t O_HBF = AL(O_HBH + SZ_HBH);
constexpr size_t O_FF  = AL(O_HBF + SZ_HBF);
constexpr size_t O_YB  = AL(O_FF  + SZ_FF);
constexpr size_t O_AP  = AL(O_YB  + SZ_YB);
constexpr size_t O_WQ  = AL(O_AP  + SZ_AP);
constexpr size_t O_WV  = AL(O_WQ  + SZ_WDD);
constexpr size_t O_WO  = AL(O_WV  + SZ_WDD);
constexpr size_t O_WK  = AL(O_WO  + SZ_WDD);
constexpr size_t O_WF1 = AL(O_WK  + SZ_WK);
constexpr size_t O_WF2 = AL(O_WF1 + SZ_WF);
constexpr size_t ARENA_BYTES = O_WF2 + SZ_WF;

__device__ __align__(256) unsigned char g_arena[ARENA_BYTES];

// ---------------- helpers ----------------
__device__ __forceinline__ void mma_f16(float* c, const uint32_t* a, const uint32_t* b) {
    asm volatile(
        "mma.sync.aligned.m16n8k16.row.col.f32.f16.f16.f32 "
        "{%0,%1,%2,%3}, {%4,%5,%6,%7}, {%8,%9}, {%0,%1,%2,%3};"
        : "+f"(c[0]), "+f"(c[1]), "+f"(c[2]), "+f"(c[3])
        : "r"(a[0]), "r"(a[1]), "r"(a[2]), "r"(a[3]), "r"(b[0]), "r"(b[1]));
}

__device__ __forceinline__ void cp16(uint32_t dst, const void* src, int sz) {
    asm volatile("cp.async.cg.shared.global [%0], [%1], 16, %2;"
                 :: "r"(dst), "l"(src), "r"(sz));
}

__device__ __forceinline__ float blk_sum256(float v, float* red8) {
    #pragma unroll
    for (int o = 16; o > 0; o >>= 1) v += __shfl_xor_sync(0xffffffffu, v, o);
    __syncthreads();
    if ((threadIdx.x & 31) == 0) red8[threadIdx.x >> 5] = v;
    __syncthreads();
    if (threadIdx.x == 0) {
        float t = 0.f;
        #pragma unroll
        for (int i = 0; i < 8; i++) t += red8[i];
        red8[0] = t;
    }
    __syncthreads();
    return red8[0];
}

__device__ __forceinline__ float blk_max256(float v, float* red8) {
    #pragma unroll
    for (int o = 16; o > 0; o >>= 1) v = fmaxf(v, __shfl_xor_sync(0xffffffffu, v, o));
    __syncthreads();
    if ((threadIdx.x & 31) == 0) red8[threadIdx.x >> 5] = v;
    __syncthreads();
    if (threadIdx.x == 0) {
        float t = -INFINITY;
        #pragma unroll
        for (int i = 0; i < 8; i++) t = fmaxf(t, red8[i]);
        red8[0] = t;
    }
    __syncthreads();
    return red8[0];
}

// ---------------- fp32 -> fp16 weight convert ----------------
__global__ void w2h_kernel(const float* __restrict__ src, __half* __restrict__ dst, int n8) {
    int i = blockIdx.x * blockDim.x + threadIdx.x;
    if (i < n8) {
        float4 a = ((const float4*)src)[2 * i];
        float4 b = ((const float4*)src)[2 * i + 1];
        __half h[8];
        h[0] = __float2half_rn(a.x); h[1] = __float2half_rn(a.y);
        h[2] = __float2half_rn(a.z); h[3] = __float2half_rn(a.w);
        h[4] = __float2half_rn(b.x); h[5] = __float2half_rn(b.y);
        h[6] = __float2half_rn(b.z); h[7] = __float2half_rn(b.w);
        ((uint4*)dst)[i] = *(const uint4*)h;
    }
}

// ---------------- LayerNorm + concat: xc_h (half, D) + xnf (fp32, E) ----------------
__global__ void ln_concat_kernel(const float* __restrict__ x,
                                 const float* __restrict__ cond,
                                 const float* __restrict__ g,
                                 const float* __restrict__ bta,
                                 __half* __restrict__ xch,
                                 float* __restrict__ xnf) {
    __shared__ float red8[8];
    const int s   = blockIdx.x;
    const int tid = threadIdx.x;
    const float* xr = x + (size_t)s * E;
    float v0 = xr[tid], v1 = xr[tid + 256], v2 = xr[tid + 512], v3 = xr[tid + 768];
    float mean = blk_sum256(v0 + v1 + v2 + v3, red8) * (1.0f / E);
    float d0 = v0 - mean, d1 = v1 - mean, d2 = v2 - mean, d3 = v3 - mean;
    float var = blk_sum256(d0 * d0 + d1 * d1 + d2 * d2 + d3 * d3, red8) * (1.0f / E);
    float rstd = rsqrtf(var + 1e-5f);
    __half* xo = xch + (size_t)s * D;
    float*  xf = xnf + (size_t)s * E;
    float r0 = d0 * rstd * g[tid      ] + bta[tid      ];
    float r1 = d1 * rstd * g[tid + 256] + bta[tid + 256];
    float r2 = d2 * rstd * g[tid + 512] + bta[tid + 512];
    float r3 = d3 * rstd * g[tid + 768] + bta[tid + 768];
    xo[tid] = __float2half_rn(r0);  xf[tid] = r0;
    xo[tid + 256] = __float2half_rn(r1);  xf[tid + 256] = r1;
    xo[tid + 512] = __float2half_rn(r2);  xf[tid + 512] = r2;
    xo[tid + 768] = __float2half_rn(r3);  xf[tid + 768] = r3;
    if (tid < CS) xo[E + tid] = __float2half_rn(cond[(size_t)s * CS + tid]);
}

// ---------------- final LayerNorm ----------------
__global__ void ln_final_kernel(const float* __restrict__ y,
                                const float* __restrict__ g,
                                const float* __restrict__ bta,
                                float* __restrict__ out) {
    __shared__ float red8[8];
    const int s   = blockIdx.x;
    const int tid = threadIdx.x;
    const float* yr = y + (size_t)s * E;
    float v0 = yr[tid], v1 = yr[tid + 256], v2 = yr[tid + 512], v3 = yr[tid + 768];
    float mean = blk_sum256(v0 + v1 + v2 + v3, red8) * (1.0f / E);
    float d0 = v0 - mean, d1 = v1 - mean, d2 = v2 - mean, d3 = v3 - mean;
    float var = blk_sum256(d0 * d0 + d1 * d1 + d2 * d2 + d3 * d3, red8) * (1.0f / E);
    float rstd = rsqrtf(var + 1e-5f);
    float* o = out + (size_t)s * E;
    o[tid      ] = d0 * rstd * g[tid      ] + bta[tid      ];
    o[tid + 256] = d1 * rstd * g[tid + 256] + bta[tid + 256];
    o[tid + 512] = d2 * rstd * g[tid + 512] + bta[tid + 512];
    o[tid + 768] = d3 * rstd * g[tid + 768] + bta[tid + 768];
}

// ---------------- build A' = w[m,c] * xc[m,d] (half) ----------------
__global__ void build_ap_kernel(const __half* __restrict__ xch,
                                const float* __restrict__ cond,
                                __half* __restrict__ ap) {
    __shared__ float xrow[D];
    __shared__ float w8[NC];
    const int m   = blockIdx.x;
    const int tid = threadIdx.x;
    if (tid < NC) w8[tid] = cond[(size_t)m * CS + tid];
    for (int d = tid; d < D; d += 256) xrow[d] = __half2float(xch[(size_t)m * D + d]);
    __syncthreads();
    __half* apr = ap + (size_t)m * (NC * D);
    #pragma unroll
    for (int c = 0; c < NC; c++) {
        float w = w8[c];
        for (int d = tid; d < D; d += 256)
            apr[c * D + d] = __float2half_rn(w * xrow[d]);
    }
}

// ---------------- row softmax on fp16 rows ----------------
__global__ void softmax_rows(__half* __restrict__ P) {
    __shared__ float red8[8];
    __half* row = P + (size_t)blockIdx.x * S;
    const int tid = threadIdx.x;
    uint4 u = ((uint4*)row)[tid];            // 8 halves
    __half* hp = (__half*)&u;
    float f[8];
    #pragma unroll
    for (int i = 0; i < 8; i++) f[i] = __half2float(hp[i]);
    float mx = f[0];
    #pragma unroll
    for (int i = 1; i < 8; i++) mx = fmaxf(mx, f[i]);
    mx = blk_max256(mx, red8);
    float sum = 0.f;
    #pragma unroll
    for (int i = 0; i < 8; i++) { f[i] = __expf(f[i] - mx); sum += f[i]; }
    sum = blk_sum256(sum, red8);
    float inv = 1.0f / sum;
    #pragma unroll
    for (int i = 0; i < 8; i++) hp[i] = __float2half_rn(f[i] * inv);
    ((uint4*)row)[tid] = u;
}

// ---------------- fp16 GEMM, cp.async double-buffered ----------------
// C(MxN) = A(MxK) * W^T, W stored [N][K] row-major (half), all ld in elements.
// MODE: 0 +bias | 1 relu(+bias) | 2 +bias+extra | 4 *scale | 5 plain | 6 +sum_c w*bk
// SCAT: 0 none | 1 -> [b,h,s,DHP] | 2 -> [b,h,dh,s] (transposed)
// SEGB: W[n][k] = Wseg[(k/segLen)*segStride + n*ldw + k%segLen]
// OUTF32: write fp32 C, else half. DUAL: also write fp32 aux (MODE 2).
// SAFEH: scalar half stores (needed when coff may be odd, e.g. PV output ldc=D, cS2=DH=65)
template <int MODE, int SCAT, bool SEGB, bool OUTF32, bool DUAL, bool SAFEH>
__global__ __launch_bounds__(256, 2)
void hgemm(const __half* __restrict__ A, int lda,
           const __half* __restrict__ W, int ldw,
           const float* __restrict__ bias,
           void* __restrict__ Cv, int ldc,
           float* __restrict__ aux,
           int N_, int K_, int Nsrc,
           const float* __restrict__ extra, int eld, float scale,
           long long aS2, long long wS2,
           long long cS1, long long cS2,
           int segLen, long long segStride) {
    __shared__ __align__(16) __half As[2][128][40];
    __shared__ __align__(16) __half Bs[2][128][40];

    const int z  = blockIdx.z;
    const __half* Ab = A + (size_t)z * aS2;
    const __half* Wb = W + (size_t)z * wS2;
    const size_t coff = (size_t)(z >> 4) * cS1 + (size_t)(z & 15) * cS2;

    const int m0  = blockIdx.y * 128;
    const int n0  = blockIdx.x * 128;
    const int tid = threadIdx.x;
    const int warp = tid >> 5;
    const int lane = tid & 31;
    const int gid  = lane >> 2;
    const int tig  = lane & 3;
    const int wm = warp & 1;
    const int wn = warp >> 1;

    const uint32_t as_base = (uint32_t)__cvta_generic_to_shared(&As[0][0][0]);
    const uint32_t bs_base = (uint32_t)__cvta_generic_to_shared(&Bs[0][0][0]);

    float acc[4][4][4];
    #pragma unroll
    for (int i = 0; i < 4; i++)
        #pragma unroll
        for (int j = 0; j < 4; j++)
            #pragma unroll
            for (int r = 0; r < 4; r++) acc[i][j][r] = 0.f;

    auto stage = [&](int st, int k0) {
        #pragma unroll
        for (int i = 0; i < 2; i++) {
            int idx = tid + (i << 8);
            int m = idx >> 2, c = idx & 3;
            int gk = k0 + c * 8;
            cp16(as_base + (uint32_t)((((st << 7) + m) * 20 + (c << 2)) << 2),
                 Ab + (size_t)(m0 + m) * lda + gk, gk < K_ ? 16 : 0);
            const __half* src;
            if constexpr (SEGB) {
                int seg = gk / segLen;
                int kl  = gk - seg * segLen;
                src = Wb + (size_t)seg * segStride + (size_t)(n0 + m) * ldw + kl;
            } else {
                src = Wb + (size_t)(n0 + m) * ldw + gk;
            }
            cp16(bs_base + (uint32_t)((((st << 7) + m) * 20 + (c << 2)) << 2),
                 src, ((n0 + m) < Nsrc && gk < K_) ? 16 : 0);
        }
    };

    stage(0, 0);
    asm volatile("cp.async.commit_group;");

    int st = 0;
    for (int k0 = 0; k0 < K_; k0 += 32) {
        if (k0 + 32 < K_) {
            stage(st ^ 1, k0 + 32);
            asm volatile("cp.async.commit_group;");
            asm volatile("cp.async.wait_group 1;");
        } else {
            asm volatile("cp.async.wait_group 0;");
        }
        __syncthreads();

        const uint32_t* A32 = (const uint32_t*)&As[0][0][0] + (size_t)st * 128 * 20;
        const uint32_t* B32 = (const uint32_t*)&Bs[0][0][0] + (size_t)st * 128 * 20;

        #pragma unroll
        for (int kb = 0; kb < 2; kb++) {
            const int wb = kb * 8;
            uint32_t af[4][4], bf[4][2];
            #pragma unroll
            for (int ms = 0; ms < 4; ms++) {
                int mrow = wm * 64 + ms * 16 + gid;
                af[ms][0] = A32[mrow * 20 + wb + tig];
                af[ms][1] = A32[(mrow + 8) * 20 + wb + tig];
                af[ms][2] = A32[mrow * 20 + wb + 4 + tig];
                af[ms][3] = A32[(mrow + 8) * 20 + wb + 4 + tig];
            }
            #pragma unroll
            for (int ns = 0; ns < 4; ns++) {
                int nrow = wn * 32 + ns * 8 + gid;
                bf[ns][0] = B32[nrow * 20 + wb + tig];
                bf[ns][1] = B32[nrow * 20 + wb + 4 + tig];
            }
            #pragma unroll
            for (int ms = 0; ms < 4; ms++)
                #pragma unroll
                for (int ns = 0; ns < 4; ns++)
                    mma_f16(acc[ms][ns], af[ms], bf[ns]);
        }
        __syncthreads();
        st ^= 1;
    }

    // ---- epilogue ----
    __half* Ch = (__half*)Cv;
    float*  Cf = (float*)Cv;

    auto epival = [&](float v, int row, int col) -> float {
        if constexpr (MODE == 0) {
            v += bias[col];
        } else if constexpr (MODE == 1) {
            v = fmaxf(v + bias[col], 0.f);
        } else if constexpr (MODE == 2) {
            v += bias[col] + extra[(size_t)row * eld + col];
        } else if constexpr (MODE == 4) {
            v *= scale;
        } else if constexpr (MODE == 6) {
            const float* wrow = extra + (size_t)row * eld;
            float bsum = 0.f;
            #pragma unroll
            for (int c = 0; c < NC; c++)
                bsum += wrow[c] * bias[(size_t)c * D + col];
            v += bsum;
        }
        return v;
    };

    #pragma unroll
    for (int ms = 0; ms < 4; ms++) {
        #pragma unroll
        for (int ns = 0; ns < 4; ns++) {
            #pragma unroll
            for (int half_r = 0; half_r < 2; half_r++) {
                const int row = m0 + wm * 64 + ms * 16 + gid + half_r * 8;
                const int col0 = n0 + wn * 32 + ns * 8 + tig * 2;
                float v0 = acc[ms][ns][half_r * 2];
                float v1 = acc[ms][ns][half_r * 2 + 1];
                if constexpr (SCAT == 0) {
                    if (col0 + 1 < N_) {
                        v0 = epival(v0, row, col0);
                        v1 = epival(v1, row, col0 + 1);
                        if constexpr (DUAL) {
                            aux[(size_t)row * ldc + col0]     = v0;
                            aux[(size_t)row * ldc + col0 + 1] = v1;
                        }
                        if constexpr (OUTF32) {
                            float2 p = make_float2(v0, v1);
                            *(float2*)&Cf[coff + (size_t)row * ldc + col0] = p;
                        } else if constexpr (SAFEH) {
                            Ch[coff + (size_t)row * ldc + col0]     = __float2half_rn(v0);
                            Ch[coff + (size_t)row * ldc + col0 + 1] = __float2half_rn(v1);
                        } else {
                            __half2 p = __floats2half2_rn(v0, v1);
                            *(__half2*)&Ch[coff + (size_t)row * ldc + col0] = p;
                        }
                    } else if (col0 < N_) {
                        v0 = epival(v0, row, col0);
                        if constexpr (DUAL) aux[(size_t)row * ldc + col0] = v0;
                        if constexpr (OUTF32) Cf[coff + (size_t)row * ldc + col0] = v0;
                        else Ch[coff + (size_t)row * ldc + col0] = __float2half_rn(v0);
                    }
                } else {
                    #pragma unroll
                    for (int e = 0; e < 2; e++) {
                        int col = col0 + e;
                        if (col < N_) {
                            float v = epival(e ? v1 : v0, row, col);
                            int b = row >> 11, s = row & (S - 1);
                            int h = col / DH;
                            int dh = col - h * DH;
                            if constexpr (SCAT == 1)
                                Ch[(((size_t)(b * H + h)) * S + s) * DHP + dh] = __float2half_rn(v);
                            else
                                Ch[(((size_t)(b * H + h)) * DHP + dh) * S + s] = __float2half_rn(v);
                        }
                    }
                }
            }
        }
    }
}

// ---------------- launcher ----------------
extern "C" void kernel_launch(void* const* d_in, const int* in_sizes, int n_in,
                              void* d_out, int out_size) {
    const float* x    = (const float*)d_in[0];
    const float* cond = (const float*)d_in[1];
    const float* Wq   = (const float*)d_in[2];
    const float* bq   = (const float*)d_in[3];
    const float* Wv   = (const float*)d_in[4];
    const float* bv   = (const float*)d_in[5];
    const float* Wk   = (const float*)d_in[6];
    const float* bk   = (const float*)d_in[7];
    const float* Wo   = (const float*)d_in[8];
    const float* bo   = (const float*)d_in[9];
    const float* g1   = (const float*)d_in[10];
    const float* bn1  = (const float*)d_in[11];
    const float* g2   = (const float*)d_in[12];
    const float* bn2  = (const float*)d_in[13];
    const float* Wf1  = (const float*)d_in[14];
    const float* bf1  = (const float*)d_in[15];
    const float* Wf2  = (const float*)d_in[16];
    const float* bf2  = (const float*)d_in[17];
    float* out = (float*)d_out;

    unsigned char* ar = nullptr;
    cudaGetSymbolAddress((void**)&ar, g_arena);
    __half* xch = (__half*)(ar + O_XCH);
    float*  xnf = (float*) (ar + O_XNF);
    __half* qp  = (__half*)(ar + O_QP);
    __half* kp  = (__half*)(ar + O_KP);
    __half* vt  = (__half*)(ar + O_VT);
    __half* ps  = (__half*)(ar + O_PS);
    __half* ob  = (__half*)(ar + O_OB);
    __half* hbh = (__half*)(ar + O_HBH);
    float*  hbf = (float*) (ar + O_HBF);
    __half* ff  = (__half*)(ar + O_FF);
    float*  yb  = (float*) (ar + O_YB);
    __half* ap  = (__half*)(ar + O_AP);
    __half* wqh = (__half*)(ar + O_WQ);
    __half* wvh = (__half*)(ar + O_WV);
    __half* woh = (__half*)(ar + O_WO);
    __half* wkh = (__half*)(ar + O_WK);
    __half* wf1h = (__half*)(ar + O_WF1);
    __half* wf2h = (__half*)(ar + O_WF2);

    const float attn_scale = 1.0f / sqrtf((float)DH);

    auto cvtw = [&](const float* src, __half* dst, size_t n) {
        int n8 = (int)(n / 8);
        w2h_kernel<<<(n8 + 255) / 256, 256>>>(src, dst, n8);
    };
    cvtw(Wq, wqh, (size_t)D * D);
    cvtw(Wv, wvh, (size_t)D * D);
    cvtw(Wo, woh, (size_t)D * D);
    cvtw(Wk, wkh, (size_t)NC * D * D);
    cvtw(Wf1, wf1h, (size_t)DFF * E);
    cvtw(Wf2, wf2h, (size_t)E * DFF);

    // 1. LN + concat
    ln_concat_kernel<<<MT, 256>>>(x, cond, g1, bn1, xch, xnf);

    // 2. A' = w * xc
    build_ap_kernel<<<MT, 256>>>(xch, cond, ap);

    const dim3 gD((D + 127) / 128, MT / 128);     // 9 x 64
    const dim3 gE(E / 128, MT / 128);             // 8 x 64
    const dim3 gF(DFF / 128, MT / 128);           // 32 x 64

    // 3. Q -> [b,h,s,DHP];  V -> transposed [b,h,dh,s]
    hgemm<0, 1, false, false, false, false><<<gD, 256>>>(
        xch, D, wqh, D, bq, qp, 0, nullptr, D, D, D,
        nullptr, 0, 0.f, 0, 0, 0, 0, 0, 0);
    hgemm<0, 2, false, false, false, false><<<gD, 256>>>(
        xch, D, wvh, D, bv, vt, 0, nullptr, D, D, D,
        nullptr, 0, 0.f, 0, 0, 0, 0, 0, 0);

    // 4. conditioned K: single GEMM K=8320 segmented over Wk[c]
    hgemm<6, 1, true, false, false, false><<<gD, 256>>>(
        ap, NC * D, wkh, D, bk, kp, 0, nullptr, D, NC * D, D,
        cond, CS, 0.f, 0, 0, 0, 0, D, (long long)D * D);

    // 5a. scores = scale * Q K^T (batched over B*H)
    {
        dim3 g(S / 128, S / 128, B * H);
        hgemm<4, 0, false, false, false, false><<<g, 256>>>(
            qp, DHP, kp, DHP, nullptr, ps, S, nullptr, S, DHP, S,
            nullptr, 0, attn_scale,
            (long long)S * DHP, (long long)S * DHP,
            (long long)H * S * S, (long long)S * S, 0, 0);
    }
    // 5b. softmax
    softmax_rows<<<B * H * S, 256>>>(ps);
    // 5c. O = P V : A=ps, B=vt (already [dh][s] per head). coff odd -> SAFEH scalar stores.
    {
        dim3 g(1, S / 128, B * H);
        hgemm<5, 0, false, false, false, true><<<g, 256>>>(
            ps, S, vt, S, nullptr, ob, D, nullptr, DH, S, DHP,
            nullptr, 0, 0.f,
            (long long)S * S, (long long)DHP * S,
            (long long)S * D, (long long)DH, 0, 0);
    }

    // 6. O-projection + residual xn -> hbh (half) + hbf (fp32)
    hgemm<2, 0, false, false, true, false><<<gE, 256>>>(
        ob, D, woh, D, bo, hbh, E, hbf, E, D, E,
        xnf, E, 0.f, 0, 0, 0, 0, 0, 0);

    // 7. FFN
    hgemm<1, 0, false, false, false, false><<<gF, 256>>>(
        hbh, E, wf1h, E, bf1, ff, DFF, nullptr, DFF, E, DFF,
        nullptr, 0, 0.f, 0, 0, 0, 0, 0, 0);
    hgemm<2, 0, false, true, false, false><<<gE, 256>>>(
        ff, DFF, wf2h, DFF, bf2, yb, E, nullptr, E, DFF, E,
        hbf, E, 0.f, 0, 0, 0, 0, 0, 0);

    // 8. final LN
    ln_final_kernel<<<MT, 256>>>(yb, g2, bn2, out);
}

// round 10
// speedup vs baseline: 11.0047x; 1.2424x over previous
#include <cuda_runtime.h>
#include <cuda_fp16.h>
#include <math.h>
#include <stdint.h>

// ---------------- problem constants ----------------
constexpr int B  = 4;
constexpr int S  = 2048;
constexpr int E  = 1024;
constexpr int CS = 16;
constexpr int NC = 8;
constexpr int H  = 16;
constexpr int D  = E + CS;      // 1040
constexpr int DH = D / H;       // 65
constexpr int DHP = 80;         // padded head dim
constexpr int DFF = 4 * E;      // 4096
constexpr int MT = B * S;       // 8192

// ---------------- arena (bytes) ----------------
constexpr size_t AL(size_t x) { return (x + 255) & ~(size_t)255; }
constexpr size_t SZ_XCH = (size_t)MT * D * 2;
constexpr size_t SZ_XNF = (size_t)MT * E * 4;
constexpr size_t SZ_HP  = (size_t)B * H * S * DHP * 2;
constexpr size_t SZ_PS  = (size_t)B * H * S * S * 2;
constexpr size_t SZ_OB  = (size_t)MT * D * 2;
constexpr size_t SZ_HBH = (size_t)MT * E * 2;
constexpr size_t SZ_HBF = (size_t)MT * E * 4;
constexpr size_t SZ_FF  = (size_t)MT * DFF * 2;
constexpr size_t SZ_YB  = (size_t)MT * E * 4;
constexpr size_t SZ_AP  = (size_t)MT * NC * D * 2;
constexpr size_t SZ_WDD = (size_t)D * D * 2;
constexpr size_t SZ_WK  = (size_t)NC * D * D * 2;
constexpr size_t SZ_WF  = (size_t)DFF * E * 2;

constexpr size_t O_XCH = 0;
constexpr size_t O_XNF = AL(O_XCH + SZ_XCH);
constexpr size_t O_QP  = AL(O_XNF + SZ_XNF);
constexpr size_t O_KP  = AL(O_QP  + SZ_HP);
constexpr size_t O_VT  = AL(O_KP  + SZ_HP);
constexpr size_t O_PS  = AL(O_VT  + SZ_HP);
constexpr size_t O_OB  = AL(O_PS  + SZ_PS);
constexpr size_t O_HBH = AL(O_OB  + SZ_OB);
constexpr size_t O_HBF = AL(O_HBH + SZ_HBH);
constexpr size_t O_FF  = AL(O_HBF + SZ_HBF);
constexpr size_t O_YB  = AL(O_FF  + SZ_FF);
constexpr size_t O_AP  = AL(O_YB  + SZ_YB);
constexpr size_t O_WQ  = AL(O_AP  + SZ_AP);
constexpr size_t O_WV  = AL(O_WQ  + SZ_WDD);
constexpr size_t O_WO  = AL(O_WV  + SZ_WDD);
constexpr size_t O_WK  = AL(O_WO  + SZ_WDD);
constexpr size_t O_WF1 = AL(O_WK  + SZ_WK);
constexpr size_t O_WF2 = AL(O_WF1 + SZ_WF);
constexpr size_t ARENA_BYTES = O_WF2 + SZ_WF;

__device__ __align__(256) unsigned char g_arena[ARENA_BYTES];

// ---------------- helpers ----------------
__device__ __forceinline__ uint32_t smem_u32(const void* p) {
    uint32_t a;
    asm("{ .reg .u64 t; cvta.to.shared.u64 t, %1; cvt.u32.u64 %0, t; }" : "=r"(a) : "l"(p));
    return a;
}

__device__ __forceinline__ void mma_f16(float* c, const uint32_t* a, const uint32_t* b) {
    asm volatile(
        "mma.sync.aligned.m16n8k16.row.col.f32.f16.f16.f32 "
        "{%0,%1,%2,%3}, {%4,%5,%6,%7}, {%8,%9}, {%0,%1,%2,%3};"
        : "+f"(c[0]), "+f"(c[1]), "+f"(c[2]), "+f"(c[3])
        : "r"(a[0]), "r"(a[1]), "r"(a[2]), "r"(a[3]), "r"(b[0]), "r"(b[1]));
}

__device__ __forceinline__ void ldm_x4(uint32_t* r, uint32_t addr) {
    asm volatile("ldmatrix.sync.aligned.m8n8.x4.shared.b16 {%0,%1,%2,%3}, [%4];"
                 : "=r"(r[0]), "=r"(r[1]), "=r"(r[2]), "=r"(r[3]) : "r"(addr));
}

__device__ __forceinline__ void cp16(uint32_t dst, const void* src, int sz) {
    asm volatile("cp.async.cg.shared.global [%0], [%1], 16, %2;"
                 :: "r"(dst), "l"(src), "r"(sz));
}

__device__ __forceinline__ float blk_sum256(float v, float* red8) {
    #pragma unroll
    for (int o = 16; o > 0; o >>= 1) v += __shfl_xor_sync(0xffffffffu, v, o);
    __syncthreads();
    if ((threadIdx.x & 31) == 0) red8[threadIdx.x >> 5] = v;
    __syncthreads();
    if (threadIdx.x == 0) {
        float t = 0.f;
        #pragma unroll
        for (int i = 0; i < 8; i++) t += red8[i];
        red8[0] = t;
    }
    __syncthreads();
    return red8[0];
}

// ---------------- fp32 -> fp16 weight convert ----------------
__global__ void w2h_kernel(const float* __restrict__ src, __half* __restrict__ dst, int n8) {
    int i = blockIdx.x * blockDim.x + threadIdx.x;
    if (i < n8) {
        float4 a = ((const float4*)src)[2 * i];
        float4 b = ((const float4*)src)[2 * i + 1];
        __half h[8];
        h[0] = __float2half_rn(a.x); h[1] = __float2half_rn(a.y);
        h[2] = __float2half_rn(a.z); h[3] = __float2half_rn(a.w);
        h[4] = __float2half_rn(b.x); h[5] = __float2half_rn(b.y);
        h[6] = __float2half_rn(b.z); h[7] = __float2half_rn(b.w);
        ((uint4*)dst)[i] = *(const uint4*)h;
    }
}

// ---------------- ones row for V^T (sum column trick) ----------------
__global__ void ones_row_kernel(__half* __restrict__ vt) {
    const size_t base = ((size_t)blockIdx.x * DHP + DH) * S;
    uint4 v;
    v.x = v.y = v.z = v.w = 0x3C003C00u;   // 1.0h x8
    ((uint4*)(vt + base))[threadIdx.x] = v;
}

// ---------------- LayerNorm + concat ----------------
__global__ void ln_concat_kernel(const float* __restrict__ x,
                                 const float* __restrict__ cond,
                                 const float* __restrict__ g,
                                 const float* __restrict__ bta,
                                 __half* __restrict__ xch,
                                 float* __restrict__ xnf) {
    __shared__ float red8[8];
    const int s   = blockIdx.x;
    const int tid = threadIdx.x;
    const float* xr = x + (size_t)s * E;
    float v0 = xr[tid], v1 = xr[tid + 256], v2 = xr[tid + 512], v3 = xr[tid + 768];
    float mean = blk_sum256(v0 + v1 + v2 + v3, red8) * (1.0f / E);
    float d0 = v0 - mean, d1 = v1 - mean, d2 = v2 - mean, d3 = v3 - mean;
    float var = blk_sum256(d0 * d0 + d1 * d1 + d2 * d2 + d3 * d3, red8) * (1.0f / E);
    float rstd = rsqrtf(var + 1e-5f);
    __half* xo = xch + (size_t)s * D;
    float*  xf = xnf + (size_t)s * E;
    float r0 = d0 * rstd * g[tid      ] + bta[tid      ];
    float r1 = d1 * rstd * g[tid + 256] + bta[tid + 256];
    float r2 = d2 * rstd * g[tid + 512] + bta[tid + 512];
    float r3 = d3 * rstd * g[tid + 768] + bta[tid + 768];
    xo[tid] = __float2half_rn(r0);  xf[tid] = r0;
    xo[tid + 256] = __float2half_rn(r1);  xf[tid + 256] = r1;
    xo[tid + 512] = __float2half_rn(r2);  xf[tid + 512] = r2;
    xo[tid + 768] = __float2half_rn(r3);  xf[tid + 768] = r3;
    if (tid < CS) xo[E + tid] = __float2half_rn(cond[(size_t)s * CS + tid]);
}

// ---------------- final LayerNorm ----------------
__global__ void ln_final_kernel(const float* __restrict__ y,
                                const float* __restrict__ g,
                                const float* __restrict__ bta,
                                float* __restrict__ out) {
    __shared__ float red8[8];
    const int s   = blockIdx.x;
    const int tid = threadIdx.x;
    const float* yr = y + (size_t)s * E;
    float v0 = yr[tid], v1 = yr[tid + 256], v2 = yr[tid + 512], v3 = yr[tid + 768];
    float mean = blk_sum256(v0 + v1 + v2 + v3, red8) * (1.0f / E);
    float d0 = v0 - mean, d1 = v1 - mean, d2 = v2 - mean, d3 = v3 - mean;
    float var = blk_sum256(d0 * d0 + d1 * d1 + d2 * d2 + d3 * d3, red8) * (1.0f / E);
    float rstd = rsqrtf(var + 1e-5f);
    float* o = out + (size_t)s * E;
    o[tid      ] = d0 * rstd * g[tid      ] + bta[tid      ];
    o[tid + 256] = d1 * rstd * g[tid + 256] + bta[tid + 256];
    o[tid + 512] = d2 * rstd * g[tid + 512] + bta[tid + 512];
    o[tid + 768] = d3 * rstd * g[tid + 768] + bta[tid + 768];
}

// ---------------- build A' = w[m,c] * xc[m,d] (half) ----------------
__global__ void build_ap_kernel(const __half* __restrict__ xch,
                                const float* __restrict__ cond,
                                __half* __restrict__ ap) {
    __shared__ float xrow[D];
    __shared__ float w8[NC];
    const int m   = blockIdx.x;
    const int tid = threadIdx.x;
    if (tid < NC) w8[tid] = cond[(size_t)m * CS + tid];
    for (int d = tid; d < D; d += 256) xrow[d] = __half2float(xch[(size_t)m * D + d]);
    __syncthreads();
    __half* apr = ap + (size_t)m * (NC * D);
    #pragma unroll
    for (int c = 0; c < NC; c++) {
        float w = w8[c];
        for (int d = tid; d < D; d += 256)
            apr[c * D + d] = __float2half_rn(w * xrow[d]);
    }
}

// ---------------- fp16 GEMM, cp.async double-buffered, ldmatrix fragments ----------------
// C(MxN) = A(MxK) * W^T, W stored [N][K] row-major (half).
// MODE: 0 +bias | 1 relu(+bias) | 2 +bias+extra | 5 plain | 6 +sum_c w*bk
//       7 exp(v*scale) | 8 plain + normalize by col DH (PV softmax denominator)
// SCAT: 0 none | 1 -> [b,h,s,DHP] | 2 -> [b,h,dh,s]
// SEGB: W[n][k] = Wseg[(k/segLen)*segStride + n*ldw + k%segLen]
// OUTF32 / DUAL / SAFEH as before.
template <int MODE, int SCAT, bool SEGB, bool OUTF32, bool DUAL, bool SAFEH>
__global__ __launch_bounds__(256, 2)
void hgemm(const __half* __restrict__ A, int lda,
           const __half* __restrict__ W, int ldw,
           const float* __restrict__ bias,
           void* __restrict__ Cv, int ldc,
           float* __restrict__ aux,
           int N_, int K_, int Nsrc,
           const float* __restrict__ extra, int eld, float scale,
           long long aS2, long long wS2,
           long long cS1, long long cS2,
           int segLen, long long segStride) {
    __shared__ __align__(16) __half As[2][128][40];
    __shared__ __align__(16) __half Bs[2][128][40];

    const int z  = blockIdx.z;
    const __half* Ab = A + (size_t)z * aS2;
    const __half* Wb = W + (size_t)z * wS2;
    const size_t coff = (size_t)(z >> 4) * cS1 + (size_t)(z & 15) * cS2;

    const int m0  = blockIdx.y * 128;
    const int n0  = blockIdx.x * 128;
    const int tid = threadIdx.x;
    const int warp = tid >> 5;
    const int lane = tid & 31;
    const int gid  = lane >> 2;
    const int tig  = lane & 3;
    const int wm = warp & 1;
    const int wn = warp >> 1;

    const uint32_t as_base = smem_u32(&As[0][0][0]);
    const uint32_t bs_base = smem_u32(&Bs[0][0][0]);

    // per-lane ldmatrix geometry
    const int arow = (lane & 7) + (((lane >> 3) & 1) << 3);
    const int akof = ((lane >> 4) & 1) << 3;
    const int brow = (lane & 7) + (((lane >> 4) & 1) << 3);
    const int bkof = ((lane >> 3) & 1) << 3;

    float acc[4][4][4];
    #pragma unroll
    for (int i = 0; i < 4; i++)
        #pragma unroll
        for (int j = 0; j < 4; j++)
            #pragma unroll
            for (int r = 0; r < 4; r++) acc[i][j][r] = 0.f;

    auto stage = [&](int st, int k0) {
        #pragma unroll
        for (int i = 0; i < 2; i++) {
            int idx = tid + (i << 8);
            int m = idx >> 2, c = idx & 3;
            int gk = k0 + c * 8;
            cp16(as_base + (uint32_t)((((st << 7) + m) * 20 + (c << 2)) << 2),
                 Ab + (size_t)(m0 + m) * lda + gk, gk < K_ ? 16 : 0);
            const __half* src;
            if constexpr (SEGB) {
                int seg = gk / segLen;
                int kl  = gk - seg * segLen;
                src = Wb + (size_t)seg * segStride + (size_t)(n0 + m) * ldw + kl;
            } else {
                src = Wb + (size_t)(n0 + m) * ldw + gk;
            }
            cp16(bs_base + (uint32_t)((((st << 7) + m) * 20 + (c << 2)) << 2),
                 src, ((n0 + m) < Nsrc && gk < K_) ? 16 : 0);
        }
    };

    stage(0, 0);
    asm volatile("cp.async.commit_group;");

    int st = 0;
    for (int k0 = 0; k0 < K_; k0 += 32) {
        if (k0 + 32 < K_) {
            stage(st ^ 1, k0 + 32);
            asm volatile("cp.async.commit_group;");
            asm volatile("cp.async.wait_group 1;");
        } else {
            asm volatile("cp.async.wait_group 0;");
        }
        __syncthreads();

        const uint32_t aO = as_base + (uint32_t)(st * 128 * 40 * 2);
        const uint32_t bO = bs_base + (uint32_t)(st * 128 * 40 * 2);

        #pragma unroll
        for (int kb = 0; kb < 2; kb++) {
            uint32_t af[4][4], bq[2][4];
            #pragma unroll
            for (int ms = 0; ms < 4; ms++)
                ldm_x4(af[ms], aO + (uint32_t)((((wm * 64 + ms * 16 + arow) * 40)
                                                + kb * 16 + akof) << 1));
            #pragma unroll
            for (int p = 0; p < 2; p++)
                ldm_x4(bq[p], bO + (uint32_t)((((wn * 32 + p * 16 + brow) * 40)
                                               + kb * 16 + bkof) << 1));
            #pragma unroll
            for (int ms = 0; ms < 4; ms++) {
                mma_f16(acc[ms][0], af[ms], &bq[0][0]);
                mma_f16(acc[ms][1], af[ms], &bq[0][2]);
                mma_f16(acc[ms][2], af[ms], &bq[1][0]);
                mma_f16(acc[ms][3], af[ms], &bq[1][2]);
            }
        }
        __syncthreads();
        st ^= 1;
    }

    // ---- PV normalization: exchange col-DH (row sums) via smem ----
    float* lrow_sm = (float*)&As[0][0][0];
    if constexpr (MODE == 8) {
        if (wn == 2 && tig == 0) {
            #pragma unroll
            for (int ms = 0; ms < 4; ms++) {
                lrow_sm[wm * 64 + ms * 16 + gid]     = acc[ms][0][1];  // col 65, row+0
                lrow_sm[wm * 64 + ms * 16 + gid + 8] = acc[ms][0][3];  // col 65, row+8
            }
        }
        __syncthreads();
    }

    // ---- epilogue ----
    __half* Ch = (__half*)Cv;
    float*  Cf = (float*)Cv;

    auto epival = [&](float v, int row, int col) -> float {
        if constexpr (MODE == 0) {
            v += bias[col];
        } else if constexpr (MODE == 1) {
            v = fmaxf(v + bias[col], 0.f);
        } else if constexpr (MODE == 2) {
            v += bias[col] + extra[(size_t)row * eld + col];
        } else if constexpr (MODE == 6) {
            const float* wrow = extra + (size_t)row * eld;
            float bsum = 0.f;
            #pragma unroll
            for (int c = 0; c < NC; c++)
                bsum += wrow[c] * bias[(size_t)c * D + col];
            v += bsum;
        } else if constexpr (MODE == 7) {
            v = __expf(v * scale);
        }
        return v;
    };

    #pragma unroll
    for (int ms = 0; ms < 4; ms++) {
        #pragma unroll
        for (int ns = 0; ns < 4; ns++) {
            #pragma unroll
            for (int half_r = 0; half_r < 2; half_r++) {
                const int row = m0 + wm * 64 + ms * 16 + gid + half_r * 8;
                const int col0 = n0 + wn * 32 + ns * 8 + tig * 2;
                float nrm = 1.f;
                if constexpr (MODE == 8)
                    nrm = 1.0f / lrow_sm[wm * 64 + ms * 16 + gid + half_r * 8];
                float v0 = acc[ms][ns][half_r * 2];
                float v1 = acc[ms][ns][half_r * 2 + 1];
                if constexpr (SCAT == 0) {
                    if (col0 + 1 < N_) {
                        v0 = epival(v0, row, col0) * nrm;
                        v1 = epival(v1, row, col0 + 1) * nrm;
                        if constexpr (DUAL) {
                            aux[(size_t)row * ldc + col0]     = v0;
                            aux[(size_t)row * ldc + col0 + 1] = v1;
                        }
                        if constexpr (OUTF32) {
                            float2 p = make_float2(v0, v1);
                            *(float2*)&Cf[coff + (size_t)row * ldc + col0] = p;
                        } else if constexpr (SAFEH) {
                            Ch[coff + (size_t)row * ldc + col0]     = __float2half_rn(v0);
                            Ch[coff + (size_t)row * ldc + col0 + 1] = __float2half_rn(v1);
                        } else {
                            __half2 p = __floats2half2_rn(v0, v1);
                            *(__half2*)&Ch[coff + (size_t)row * ldc + col0] = p;
                        }
                    } else if (col0 < N_) {
                        v0 = epival(v0, row, col0) * nrm;
                        if constexpr (DUAL) aux[(size_t)row * ldc + col0] = v0;
                        if constexpr (OUTF32) Cf[coff + (size_t)row * ldc + col0] = v0;
                        else Ch[coff + (size_t)row * ldc + col0] = __float2half_rn(v0);
                    }
                } else {
                    #pragma unroll
                    for (int e = 0; e < 2; e++) {
                        int col = col0 + e;
                        if (col < N_) {
                            float v = epival(e ? v1 : v0, row, col);
                            int bb = row >> 11, s = row & (S - 1);
                            int h = col / DH;
                            int dh = col - h * DH;
                            if constexpr (SCAT == 1)
                                Ch[(((size_t)(bb * H + h)) * S + s) * DHP + dh] =
                                    __float2half_rn(v);
                            else
                                Ch[(((size_t)(bb * H + h)) * DHP + dh) * S + s] =
                                    __float2half_rn(v);
                        }
                    }
                }
            }
        }
    }
}

// ---------------- launcher ----------------
extern "C" void kernel_launch(void* const* d_in, const int* in_sizes, int n_in,
                              void* d_out, int out_size) {
    const float* x    = (const float*)d_in[0];
    const float* cond = (const float*)d_in[1];
    const float* Wq   = (const float*)d_in[2];
    const float* bq   = (const float*)d_in[3];
    const float* Wv   = (const float*)d_in[4];
    const float* bv   = (const float*)d_in[5];
    const float* Wk   = (const float*)d_in[6];
    const float* bk   = (const float*)d_in[7];
    const float* Wo   = (const float*)d_in[8];
    const float* bo   = (const float*)d_in[9];
    const float* g1   = (const float*)d_in[10];
    const float* bn1  = (const float*)d_in[11];
    const float* g2   = (const float*)d_in[12];
    const float* bn2  = (const float*)d_in[13];
    const float* Wf1  = (const float*)d_in[14];
    const float* bf1  = (const float*)d_in[15];
    const float* Wf2  = (const float*)d_in[16];
    const float* bf2  = (const float*)d_in[17];
    float* out = (float*)d_out;

    unsigned char* ar = nullptr;
    cudaGetSymbolAddress((void**)&ar, g_arena);
    __half* xch = (__half*)(ar + O_XCH);
    float*  xnf = (float*) (ar + O_XNF);
    __half* qp  = (__half*)(ar + O_QP);
    __half* kp  = (__half*)(ar + O_KP);
    __half* vt  = (__half*)(ar + O_VT);
    __half* ps  = (__half*)(ar + O_PS);
    __half* ob  = (__half*)(ar + O_OB);
    __half* hbh = (__half*)(ar + O_HBH);
    float*  hbf = (float*) (ar + O_HBF);
    __half* ff  = (__half*)(ar + O_FF);
    float*  yb  = (float*) (ar + O_YB);
    __half* ap  = (__half*)(ar + O_AP);
    __half* wqh = (__half*)(ar + O_WQ);
    __half* wvh = (__half*)(ar + O_WV);
    __half* woh = (__half*)(ar + O_WO);
    __half* wkh = (__half*)(ar + O_WK);
    __half* wf1h = (__half*)(ar + O_WF1);
    __half* wf2h = (__half*)(ar + O_WF2);

    const float attn_scale = 1.0f / sqrtf((float)DH);

    auto cvtw = [&](const float* src, __half* dst, size_t n) {
        int n8 = (int)(n / 8);
        w2h_kernel<<<(n8 + 255) / 256, 256>>>(src, dst, n8);
    };
    cvtw(Wq, wqh, (size_t)D * D);
    cvtw(Wv, wvh, (size_t)D * D);
    cvtw(Wo, woh, (size_t)D * D);
    cvtw(Wk, wkh, (size_t)NC * D * D);
    cvtw(Wf1, wf1h, (size_t)DFF * E);
    cvtw(Wf2, wf2h, (size_t)E * DFF);

    // ones row (dh==DH) of V^T for the row-sum column
    ones_row_kernel<<<B * H, 256>>>(vt);

    // 1. LN + concat
    ln_concat_kernel<<<MT, 256>>>(x, cond, g1, bn1, xch, xnf);

    // 2. A' = w * xc
    build_ap_kernel<<<MT, 256>>>(xch, cond, ap);

    const dim3 gD((D + 127) / 128, MT / 128);     // 9 x 64
    const dim3 gE(E / 128, MT / 128);             // 8 x 64
    const dim3 gF(DFF / 128, MT / 128);           // 32 x 64

    // 3. Q -> [b,h,s,DHP];  V -> transposed [b,h,dh,s] (rows 0..64)
    hgemm<0, 1, false, false, false, false><<<gD, 256>>>(
        xch, D, wqh, D, bq, qp, 0, nullptr, D, D, D,
        nullptr, 0, 0.f, 0, 0, 0, 0, 0, 0);
    hgemm<0, 2, false, false, false, false><<<gD, 256>>>(
        xch, D, wvh, D, bv, vt, 0, nullptr, D, D, D,
        nullptr, 0, 0.f, 0, 0, 0, 0, 0, 0);

    // 4. conditioned K: single GEMM K=8320 segmented over Wk[c]
    hgemm<6, 1, true, false, false, false><<<gD, 256>>>(
        ap, NC * D, wkh, D, bk, kp, 0, nullptr, D, NC * D, D,
        cond, CS, 0.f, 0, 0, 0, 0, D, (long long)D * D);

    // 5a. P = exp(scale * Q K^T), unnormalized (batched over B*H)
    {
        dim3 g(S / 128, S / 128, B * H);
        hgemm<7, 0, false, false, false, false><<<g, 256>>>(
            qp, DHP, kp, DHP, nullptr, ps, S, nullptr, S, DHP, S,
            nullptr, 0, attn_scale,
            (long long)S * DHP, (long long)S * DHP,
            (long long)H * S * S, (long long)S * S, 0, 0);
    }
    // 5b. O = (P V) / rowsum  — ones-column (row 65) gives rowsum in col 65
    {
        dim3 g(1, S / 128, B * H);
        hgemm<8, 0, false, false, false, true><<<g, 256>>>(
            ps, S, vt, S, nullptr, ob, D, nullptr, DH, S, DH + 1,
            nullptr, 0, 0.f,
            (long long)S * S, (long long)DHP * S,
            (long long)S * D, (long long)DH, 0, 0);
    }

    // 6. O-projection + residual xn -> hbh (half) + hbf (fp32)
    hgemm<2, 0, false, false, true, false><<<gE, 256>>>(
        ob, D, woh, D, bo, hbh, E, hbf, E, D, E,
        xnf, E, 0.f, 0, 0, 0, 0, 0, 0);

    // 7. FFN
    hgemm<1, 0, false, false, false, false><<<gF, 256>>>(
        hbh, E, wf1h, E, bf1, ff, DFF, nullptr, DFF, E, DFF,
        nullptr, 0, 0.f, 0, 0, 0, 0, 0, 0);
    hgemm<2, 0, false, true, false, false><<<gE, 256>>>(
        ff, DFF, wf2h, DFF, bf2, yb, E, nullptr, E, DFF, E,
        hbf, E, 0.f, 0, 0, 0, 0, 0, 0);

    // 8. final LN
    ln_final_kernel<<<MT, 256>>>(yb, g2, bn2, out);
}